// round 1
// baseline (speedup 1.0000x reference)
#include <cuda_runtime.h>
#include <cstdint>
#include <cstddef>

// ---------------- problem constants ----------------
#define BATCH 16
#define NQ    512
#define NK    1024
#define DH    128
#define HEADS 8
#define BH    (BATCH*HEADS)        // 128
#define SCALE 0.08838834764831845f // 1/sqrt(128)

// ---------------- GEMM tiling ----------------
#define BK   32
#define BKP  36                    // BK + 4 pad -> conflict-free frag loads

// ---------------- device scratch (no allocs allowed) ----------------
__device__ float g_u   [(size_t)BH*NQ*DH];      // [B,H,NQ,DH]
__device__ float g_gg  [(size_t)BH*NQ*DH];      // [B,H,NQ,DH]
__device__ float g_v   [(size_t)BH*NK*DH];      // [B,H,NK,DH]
__device__ float g_p   [(size_t)BH*NK*DH];      // [B,H,NK,DH]
__device__ float g_att [(size_t)BH*NQ*NK];      // [B,H,NQ,NK]  (256 MB)
__device__ float g_rowmax[BH*NQ];
__device__ float g_rowsum[BH*NQ];
__device__ float g_colmax[BH*NK];
__device__ float g_colsum[BH*NK];
__device__ float g_Pmid[(size_t)BATCH*NQ*HEADS*DH]; // [B,NQ,H,DH]
__device__ float g_Dmid[(size_t)BATCH*NK*HEADS*DH]; // [B,NK,H,DH]

// ---------------- helpers ----------------
__device__ __forceinline__ float tf32r(float x){
    uint32_t u; asm("cvt.rna.tf32.f32 %0, %1;" : "=r"(u) : "f"(x));
    return __uint_as_float(u);
}

__device__ __forceinline__ void mma8(float (&c)[4], const uint32_t (&a)[4], const uint32_t (&b)[2]){
    asm volatile("mma.sync.aligned.m16n8k8.row.col.f32.tf32.tf32.f32 "
        "{%0,%1,%2,%3}, {%4,%5,%6,%7}, {%8,%9}, {%0,%1,%2,%3};"
        : "+f"(c[0]),"+f"(c[1]),"+f"(c[2]),"+f"(c[3])
        : "r"(a[0]),"r"(a[1]),"r"(a[2]),"r"(a[3]), "r"(b[0]),"r"(b[1]));
}

// Warp computes 32x32 from smem tiles (k-contig, stride BKP). MI=2 m-frags, NI=4 n-frags.
__device__ __forceinline__ void mma_slab(const float* As_w, const float* Bs_w,
                                         float (&c)[2][4][4], int lane){
    const int group = lane >> 2, tq = lane & 3;
    #pragma unroll
    for (int kk = 0; kk < BK; kk += 8) {
        uint32_t a[2][4], b[4][2];
        #pragma unroll
        for (int mi = 0; mi < 2; mi++){
            const float* ap = As_w + (mi*16 + group)*BKP + kk + tq;
            a[mi][0] = __float_as_uint(ap[0]);
            a[mi][1] = __float_as_uint(ap[8*BKP]);
            a[mi][2] = __float_as_uint(ap[4]);
            a[mi][3] = __float_as_uint(ap[8*BKP+4]);
        }
        #pragma unroll
        for (int ni = 0; ni < 4; ni++){
            const float* bp = Bs_w + (ni*8 + group)*BKP + kk + tq;
            b[ni][0] = __float_as_uint(bp[0]);
            b[ni][1] = __float_as_uint(bp[4]);
        }
        #pragma unroll
        for (int mi = 0; mi < 2; mi++)
            #pragma unroll
            for (int ni = 0; ni < 4; ni++)
                mma8(c[mi][ni], a[mi], b[ni]);
    }
}

// ---------------- smem tile loaders (256-thread CTAs) ----------------
// 128 rows x 32 k, row-major source, float4
__device__ __forceinline__ void load_A_128x32(float* As, const float* src, size_t stride){
    int fc = threadIdx.x & 7, r0 = threadIdx.x >> 3;
    #pragma unroll
    for (int it = 0; it < 4; it++){
        int row = r0 + it*32;
        float4 v = *(const float4*)(src + (size_t)row*stride + fc*4);
        float* d = &As[row*BKP + fc*4];
        d[0]=tf32r(v.x); d[1]=tf32r(v.y); d[2]=tf32r(v.z); d[3]=tf32r(v.w);
    }
}
// same but apply exp(x - rowmax[row])
__device__ __forceinline__ void load_A_exp_128x32(float* As, const float* src, size_t stride,
                                                  const float* __restrict__ rmax){
    int fc = threadIdx.x & 7, r0 = threadIdx.x >> 3;
    #pragma unroll
    for (int it = 0; it < 4; it++){
        int row = r0 + it*32;
        float rm = __ldg(rmax + row);
        float4 v = *(const float4*)(src + (size_t)row*stride + fc*4);
        float* d = &As[row*BKP + fc*4];
        d[0]=tf32r(__expf(v.x-rm)); d[1]=tf32r(__expf(v.y-rm));
        d[2]=tf32r(__expf(v.z-rm)); d[3]=tf32r(__expf(v.w-rm));
    }
}
// 64 rows x 32 k, row-major source (already [n][k])
__device__ __forceinline__ void load_B_64x32(float* Bs, const float* src, size_t stride){
    int fc = threadIdx.x & 7, r0 = threadIdx.x >> 3;
    #pragma unroll
    for (int it = 0; it < 2; it++){
        int row = r0 + it*32;
        float4 v = *(const float4*)(src + (size_t)row*stride + fc*4);
        float* d = &Bs[row*BKP + fc*4];
        d[0]=tf32r(v.x); d[1]=tf32r(v.y); d[2]=tf32r(v.z); d[3]=tf32r(v.w);
    }
}
// source tile is [32 k rows][64 n cols] row-major -> Bs[n][k] (transpose)
__device__ __forceinline__ void load_B_T_32x64(float* Bs, const float* src, size_t stride){
    int tx = threadIdx.x & 63, r0 = threadIdx.x >> 6;
    #pragma unroll
    for (int it = 0; it < 8; it++){
        int k = r0 + it*4;
        Bs[tx*BKP + k] = tf32r(src[(size_t)k*stride + tx]);
    }
}
// source tile [32 q rows][128 key cols] -> As[key][q], apply exp(x - colmax[key])
__device__ __forceinline__ void load_A_T_exp_32x128(float* As, const float* src, size_t stride,
                                                    const float* __restrict__ cmax){
    int tx = threadIdx.x & 127, r0 = threadIdx.x >> 7;
    float cm = __ldg(cmax + tx);
    #pragma unroll
    for (int it = 0; it < 16; it++){
        int q = r0 + it*2;
        As[tx*BKP + q] = tf32r(__expf(src[(size_t)q*stride + tx] - cm));
    }
}

// ---------------- kernel 1: input projections with head scatter ----------------
// C[M=B*Nrows,1024] = X[M,128] @ W[1024,128]^T + bias, scattered to Y[B,H,Nrows,128]
__global__ void __launch_bounds__(256)
proj_head_kernel(const float* __restrict__ X, const float* __restrict__ W,
                 const float* __restrict__ bias, float* __restrict__ Y, int Nrows){
    __shared__ float As[128*BKP];
    __shared__ float Bs[64*BKP];
    int m0 = blockIdx.x*128, n0 = blockIdx.y*64;
    int warp = threadIdx.x>>5, lane = threadIdx.x&31;
    int wm = warp>>1, wn = warp&1;
    float c[2][4][4] = {};
    for (int ks = 0; ks < 128; ks += BK){
        load_A_128x32(As, X + (size_t)m0*128 + ks, 128);
        load_B_64x32(Bs, W + (size_t)n0*128 + ks, 128);
        __syncthreads();
        mma_slab(&As[wm*32*BKP], &Bs[wn*32*BKP], c, lane);
        __syncthreads();
    }
    int group = lane>>2, tq = lane&3;
    #pragma unroll
    for (int mi=0;mi<2;mi++)
    #pragma unroll
    for (int ni=0;ni<4;ni++)
    #pragma unroll
    for (int r=0;r<4;r++){
        int row = m0 + wm*32 + mi*16 + group + ((r>>1)<<3);
        int col = n0 + wn*32 + ni*8 + tq*2 + (r&1);
        int b = row / Nrows, n = row - b*Nrows;
        int h = col >> 7, d = col & 127;
        Y[(((size_t)(b*HEADS + h)*Nrows + n) << 7) + d] = c[mi][ni][r] + bias[col];
    }
}

// ---------------- kernel 2: scores att = (u @ v^T) * scale ----------------
__global__ void __launch_bounds__(256)
scores_kernel(){
    __shared__ float As[128*BKP];
    __shared__ float Bs[64*BKP];
    int bh = blockIdx.z;
    int m0 = blockIdx.x*128, n0 = blockIdx.y*64;
    const float* U = g_u + (size_t)bh*NQ*DH;
    const float* V = g_v + (size_t)bh*NK*DH;
    int warp = threadIdx.x>>5, lane = threadIdx.x&31;
    int wm = warp>>1, wn = warp&1;
    float c[2][4][4] = {};
    for (int ks = 0; ks < 128; ks += BK){
        load_A_128x32(As, U + (size_t)m0*DH + ks, DH);
        load_B_64x32(Bs, V + (size_t)n0*DH + ks, DH);
        __syncthreads();
        mma_slab(&As[wm*32*BKP], &Bs[wn*32*BKP], c, lane);
        __syncthreads();
    }
    int group = lane>>2, tq = lane&3;
    float* att = g_att + (size_t)bh*NQ*NK;
    #pragma unroll
    for (int mi=0;mi<2;mi++)
    #pragma unroll
    for (int ni=0;ni<4;ni++)
    #pragma unroll
    for (int r=0;r<4;r++){
        int row = m0 + wm*32 + mi*16 + group + ((r>>1)<<3);
        int col = n0 + wn*32 + ni*8 + tq*2 + (r&1);
        att[(size_t)row*NK + col] = c[mi][ni][r] * SCALE;
    }
}

// ---------------- kernel 3: row stats (softmax over k) ----------------
__global__ void __launch_bounds__(256)
rowstats_kernel(){
    int row = blockIdx.x;                 // bh*NQ + q
    const float* p = g_att + (size_t)row*NK;
    int tid = threadIdx.x;
    float4 v = *(const float4*)(p + tid*4);
    float m = fmaxf(fmaxf(v.x,v.y), fmaxf(v.z,v.w));
    #pragma unroll
    for (int o=16;o;o>>=1) m = fmaxf(m, __shfl_xor_sync(0xffffffffu, m, o));
    __shared__ float sm[8];
    if ((tid&31)==0) sm[tid>>5] = m;
    __syncthreads();
    if (tid < 32){
        float mm = (tid < 8) ? sm[tid] : -1e30f;
        #pragma unroll
        for (int o=4;o;o>>=1) mm = fmaxf(mm, __shfl_xor_sync(0xffffffffu, mm, o));
        if (tid==0) sm[0] = mm;
    }
    __syncthreads();
    m = sm[0];
    float s = __expf(v.x-m)+__expf(v.y-m)+__expf(v.z-m)+__expf(v.w-m);
    #pragma unroll
    for (int o=16;o;o>>=1) s += __shfl_xor_sync(0xffffffffu, s, o);
    __shared__ float ssm[8];
    if ((tid&31)==0) ssm[tid>>5] = s;
    __syncthreads();
    if (tid == 0){
        float t = 0.f;
        #pragma unroll
        for (int i=0;i<8;i++) t += ssm[i];
        g_rowmax[row] = m; g_rowsum[row] = t;
    }
}

// ---------------- kernel 4: column stats (softmax over q) ----------------
__global__ void __launch_bounds__(256)
colstats_kernel(){
    int bh = blockIdx.y;
    int k = blockIdx.x*64 + threadIdx.x;  // blockDim = (64,4)
    int ty = threadIdx.y;
    float m = -1e30f, s = 0.f;
    const float* base = g_att + (size_t)bh*NQ*NK + k;
    for (int q = ty; q < NQ; q += 4){
        float x = base[(size_t)q*NK];
        float mn = fmaxf(m, x);
        s = s*__expf(m-mn) + __expf(x-mn);
        m = mn;
    }
    __shared__ float sm[4][64], ss[4][64];
    sm[ty][threadIdx.x] = m; ss[ty][threadIdx.x] = s;
    __syncthreads();
    if (ty == 0){
        float M = sm[0][threadIdx.x], S = ss[0][threadIdx.x];
        #pragma unroll
        for (int j=1;j<4;j++){
            float mj = sm[j][threadIdx.x];
            float mn = fmaxf(M, mj);
            S = S*__expf(M-mn) + ss[j][threadIdx.x]*__expf(mj-mn);
            M = mn;
        }
        g_colmax[bh*NK + k] = M; g_colsum[bh*NK + k] = S;
    }
}

// ---------------- kernel 5: P = softmax_row(att) @ p ----------------
__global__ void __launch_bounds__(256)
pgemm_kernel(){
    __shared__ float As[128*BKP];
    __shared__ float Bs[64*BKP];
    int bh = blockIdx.z;
    int m0 = blockIdx.x*128, n0 = blockIdx.y*64;
    const float* att = g_att + (size_t)bh*NQ*NK;
    const float* P = g_p + (size_t)bh*NK*DH;
    const float* rmax = g_rowmax + bh*NQ + m0;
    int warp = threadIdx.x>>5, lane = threadIdx.x&31;
    int wm = warp>>1, wn = warp&1;
    float c[2][4][4] = {};
    for (int ks = 0; ks < NK; ks += BK){
        load_A_exp_128x32(As, att + (size_t)m0*NK + ks, NK, rmax);
        load_B_T_32x64(Bs, P + (size_t)ks*DH + n0, DH);
        __syncthreads();
        mma_slab(&As[wm*32*BKP], &Bs[wn*32*BKP], c, lane);
        __syncthreads();
    }
    int group = lane>>2, tq = lane&3;
    int b = bh >> 3, h = bh & 7;
    #pragma unroll
    for (int mi=0;mi<2;mi++)
    #pragma unroll
    for (int ni=0;ni<4;ni++)
    #pragma unroll
    for (int r=0;r<4;r++){
        int row = m0 + wm*32 + mi*16 + group + ((r>>1)<<3);
        int col = n0 + wn*32 + ni*8 + tq*2 + (r&1);
        float inv = 1.0f / __ldg(&g_rowsum[bh*NQ + row]);
        g_Pmid[(((size_t)(b*NQ + row)*HEADS + h) << 7) + col] = c[mi][ni][r] * inv;
    }
}

// ---------------- kernel 6: D = softmax_col(att)^T @ g ----------------
__global__ void __launch_bounds__(256)
dgemm_kernel(){
    __shared__ float As[128*BKP];
    __shared__ float Bs[64*BKP];
    int bh = blockIdx.z;
    int m0 = blockIdx.x*128, n0 = blockIdx.y*64;   // m = key index
    const float* att = g_att + (size_t)bh*NQ*NK;
    const float* G = g_gg + (size_t)bh*NQ*DH;
    const float* cmax = g_colmax + bh*NK + m0;
    int warp = threadIdx.x>>5, lane = threadIdx.x&31;
    int wm = warp>>1, wn = warp&1;
    float c[2][4][4] = {};
    for (int ks = 0; ks < NQ; ks += BK){
        load_A_T_exp_32x128(As, att + (size_t)ks*NK + m0, NK, cmax);
        load_B_T_32x64(Bs, G + (size_t)ks*DH + n0, DH);
        __syncthreads();
        mma_slab(&As[wm*32*BKP], &Bs[wn*32*BKP], c, lane);
        __syncthreads();
    }
    int group = lane>>2, tq = lane&3;
    int b = bh >> 3, h = bh & 7;
    #pragma unroll
    for (int mi=0;mi<2;mi++)
    #pragma unroll
    for (int ni=0;ni<4;ni++)
    #pragma unroll
    for (int r=0;r<4;r++){
        int row = m0 + wm*32 + mi*16 + group + ((r>>1)<<3);  // key
        int col = n0 + wn*32 + ni*8 + tq*2 + (r&1);          // dv
        float inv = 1.0f / __ldg(&g_colsum[bh*NK + row]);
        g_Dmid[(((size_t)(b*NK + row)*HEADS + h) << 7) + col] = c[mi][ni][r] * inv;
    }
}

// ---------------- kernel 7: output projection (row-major out) ----------------
// C[M,128] = X[M,1024] @ W[128,1024]^T + bias
__global__ void __launch_bounds__(256)
outproj_kernel(const float* __restrict__ X, const float* __restrict__ W,
               const float* __restrict__ bias, float* __restrict__ out){
    __shared__ float As[128*BKP];
    __shared__ float Bs[64*BKP];
    int m0 = blockIdx.x*128, n0 = blockIdx.y*64;
    int warp = threadIdx.x>>5, lane = threadIdx.x&31;
    int wm = warp>>1, wn = warp&1;
    float c[2][4][4] = {};
    for (int ks = 0; ks < 1024; ks += BK){
        load_A_128x32(As, X + (size_t)m0*1024 + ks, 1024);
        load_B_64x32(Bs, W + (size_t)n0*1024 + ks, 1024);
        __syncthreads();
        mma_slab(&As[wm*32*BKP], &Bs[wn*32*BKP], c, lane);
        __syncthreads();
    }
    int group = lane>>2, tq = lane&3;
    #pragma unroll
    for (int mi=0;mi<2;mi++)
    #pragma unroll
    for (int ni=0;ni<4;ni++)
    #pragma unroll
    for (int r=0;r<4;r++){
        int row = m0 + wm*32 + mi*16 + group + ((r>>1)<<3);
        int col = n0 + wn*32 + ni*8 + tq*2 + (r&1);
        out[((size_t)row << 7) + col] = c[mi][ni][r] + bias[col];
    }
}

// ---------------- launch ----------------
extern "C" void kernel_launch(void* const* d_in, const int* in_sizes, int n_in,
                              void* d_out, int out_size){
    const float* queries = (const float*)d_in[0];
    const float* keys    = (const float*)d_in[1];
    const float* Wq  = (const float*)d_in[2];
    const float* bq  = (const float*)d_in[3];
    const float* Wk  = (const float*)d_in[4];
    const float* bk  = (const float*)d_in[5];
    const float* Wp  = (const float*)d_in[6];
    const float* bp  = (const float*)d_in[7];
    const float* Wg  = (const float*)d_in[8];
    const float* bg  = (const float*)d_in[9];
    const float* Wo1 = (const float*)d_in[10];
    const float* bo1 = (const float*)d_in[11];
    const float* Wo2 = (const float*)d_in[12];
    const float* bo2 = (const float*)d_in[13];
    float* out = (float*)d_out;

    float *pu, *pg, *pv, *pp, *pPmid, *pDmid;
    cudaGetSymbolAddress((void**)&pu,    g_u);
    cudaGetSymbolAddress((void**)&pg,    g_gg);
    cudaGetSymbolAddress((void**)&pv,    g_v);
    cudaGetSymbolAddress((void**)&pp,    g_p);
    cudaGetSymbolAddress((void**)&pPmid, g_Pmid);
    cudaGetSymbolAddress((void**)&pDmid, g_Dmid);

    // projections: u,g from queries (M=8192); v,p from keys (M=16384)
    proj_head_kernel<<<dim3(64,16),  256>>>(queries, Wq, bq, pu, NQ);
    proj_head_kernel<<<dim3(64,16),  256>>>(queries, Wg, bg, pg, NQ);
    proj_head_kernel<<<dim3(128,16), 256>>>(keys,    Wk, bk, pv, NK);
    proj_head_kernel<<<dim3(128,16), 256>>>(keys,    Wp, bp, pp, NK);

    // shared score matrix
    scores_kernel<<<dim3(NQ/128, NK/64, BH), 256>>>();

    // softmax stats
    rowstats_kernel<<<BH*NQ, 256>>>();
    colstats_kernel<<<dim3(NK/64, BH), dim3(64,4)>>>();

    // attention-value GEMMs
    pgemm_kernel<<<dim3(NQ/128, DH/64, BH), 256>>>();
    dgemm_kernel<<<dim3(NK/128, DH/64, BH), 256>>>();

    // output projections: P first, then D, concatenated in d_out
    outproj_kernel<<<dim3(BATCH*NQ/128, 2), 256>>>(pPmid, Wo1, bo1, out);
    outproj_kernel<<<dim3(BATCH*NK/128, 2), 256>>>(pDmid, Wo2, bo2, out + (size_t)BATCH*NQ*DH);
}

// round 2
// speedup vs baseline: 1.1399x; 1.1399x over previous
#include <cuda_runtime.h>
#include <cstdint>
#include <cstddef>

// ---------------- problem constants ----------------
#define BATCH 16
#define NQ    512
#define NK    1024
#define DH    128
#define HEADS 8
#define BH    (BATCH*HEADS)        // 128
#define SCALE 0.08838834764831845f // 1/sqrt(128)

// ---------------- GEMM tiling ----------------
#define BK   32
#define BKP  36                    // BK + 4 pad -> conflict-free frag loads
#define TRP  136                   // transpose-staging stride (8-mult, conflict-free both ways)
#define SMEM_FLOATS (2*128*BKP + 2*64*BKP)   // 13824 floats = 55296 B
#define SMEM_BYTES  (SMEM_FLOATS*4)

// ---------------- device scratch ----------------
__device__ float g_u  [(size_t)BH*NQ*DH];      // [bh][nq][dh]
__device__ float g_v  [(size_t)BH*NK*DH];      // [bh][nk][dh]
__device__ float g_pT [(size_t)BH*DH*NK];      // [bh][dh][nk]  (transposed p)
__device__ float g_gT [(size_t)BH*DH*NQ];      // [bh][dh][nq]  (transposed g)
__device__ float g_E  [(size_t)BH*NQ*NK];      // exp(att)      (tf32-rounded)
__device__ float g_ET [(size_t)BH*NK*NQ];      // exp(att)^T
__device__ float g_rowsum[BH*NQ];
__device__ float g_colsum[BH*NK];
__device__ float g_Pmid[(size_t)BATCH*NQ*HEADS*DH]; // [b,q,h,d]
__device__ float g_Dmid[(size_t)BATCH*NK*HEADS*DH]; // [b,k,h,d]

// ---------------- helpers ----------------
__device__ __forceinline__ float tf32r(float x){
    uint32_t u; asm("cvt.rna.tf32.f32 %0, %1;" : "=r"(u) : "f"(x));
    return __uint_as_float(u);
}

__device__ __forceinline__ void mma8(float (&c)[4], const uint32_t (&a)[4], const uint32_t (&b)[2]){
    asm volatile("mma.sync.aligned.m16n8k8.row.col.f32.tf32.tf32.f32 "
        "{%0,%1,%2,%3}, {%4,%5,%6,%7}, {%8,%9}, {%0,%1,%2,%3};"
        : "+f"(c[0]),"+f"(c[1]),"+f"(c[2]),"+f"(c[3])
        : "r"(a[0]),"r"(a[1]),"r"(a[2]),"r"(a[3]), "r"(b[0]),"r"(b[1]));
}

// Warp computes 32x32 from smem tiles (k-contig, stride BKP).
__device__ __forceinline__ void mma_slab(const float* As_w, const float* Bs_w,
                                         float (&c)[2][4][4], int lane){
    const int group = lane >> 2, tq = lane & 3;
    #pragma unroll
    for (int kk = 0; kk < BK; kk += 8) {
        uint32_t a[2][4], b[4][2];
        #pragma unroll
        for (int mi = 0; mi < 2; mi++){
            const float* ap = As_w + (mi*16 + group)*BKP + kk + tq;
            a[mi][0] = __float_as_uint(ap[0]);
            a[mi][1] = __float_as_uint(ap[8*BKP]);
            a[mi][2] = __float_as_uint(ap[4]);
            a[mi][3] = __float_as_uint(ap[8*BKP+4]);
        }
        #pragma unroll
        for (int ni = 0; ni < 4; ni++){
            const float* bp = Bs_w + (ni*8 + group)*BKP + kk + tq;
            b[ni][0] = __float_as_uint(bp[0]);
            b[ni][1] = __float_as_uint(bp[4]);
        }
        #pragma unroll
        for (int mi = 0; mi < 2; mi++)
            #pragma unroll
            for (int ni = 0; ni < 4; ni++)
                mma8(c[mi][ni], a[mi], b[ni]);
    }
}

// -------- register-double-buffered pipelined GEMM core --------
// C[128x64] += A[128xK] * B[64xK]^T, both row-major k-contiguous.
template<bool CVTA, bool CVTB>
__device__ __forceinline__ void gemm_pipe(const float* __restrict__ A, int lda,
                                          const float* __restrict__ B, int ldb,
                                          int K, float (&c)[2][4][4],
                                          float* smbuf, int wm, int wn, int lane)
{
    const int fc = (threadIdx.x & 7) << 2;
    const int r0 = threadIdx.x >> 3;
    float4 ra[4], rb[2];
    #pragma unroll
    for (int i = 0; i < 4; i++) ra[i] = *(const float4*)(A + (size_t)(r0+32*i)*lda + fc);
    #pragma unroll
    for (int i = 0; i < 2; i++) rb[i] = *(const float4*)(B + (size_t)(r0+32*i)*ldb + fc);

    int buf = 0;
    for (int ks = BK;; ks += BK){
        float* As = smbuf + buf*(128*BKP);
        float* Bs = smbuf + 2*128*BKP + buf*(64*BKP);
        #pragma unroll
        for (int i = 0; i < 4; i++){
            float* d = &As[(r0+32*i)*BKP + fc];
            if (CVTA){ d[0]=tf32r(ra[i].x); d[1]=tf32r(ra[i].y); d[2]=tf32r(ra[i].z); d[3]=tf32r(ra[i].w); }
            else     { *(float4*)d = ra[i]; }
        }
        #pragma unroll
        for (int i = 0; i < 2; i++){
            float* d = &Bs[(r0+32*i)*BKP + fc];
            if (CVTB){ d[0]=tf32r(rb[i].x); d[1]=tf32r(rb[i].y); d[2]=tf32r(rb[i].z); d[3]=tf32r(rb[i].w); }
            else     { *(float4*)d = rb[i]; }
        }
        __syncthreads();
        if (ks < K){
            #pragma unroll
            for (int i = 0; i < 4; i++) ra[i] = *(const float4*)(A + ks + (size_t)(r0+32*i)*lda + fc);
            #pragma unroll
            for (int i = 0; i < 2; i++) rb[i] = *(const float4*)(B + ks + (size_t)(r0+32*i)*ldb + fc);
        }
        mma_slab(As + wm*32*BKP, Bs + wn*32*BKP, c, lane);
        if (ks >= K) break;
        buf ^= 1;
    }
    __syncthreads();   // smem safe to reuse (epilogue staging)
}

// ---------------- kernel 1: input projections ----------------
// C[M,1024] = X[M,128] @ W[1024,128]^T + bias
// TRANS=false: scatter to Y[bh][n][128] ; TRANS=true: scatter to Y[bh][d][Nrows]
template<bool TRANS>
__global__ void __launch_bounds__(256)
proj_kernel(const float* __restrict__ X, const float* __restrict__ W,
            const float* __restrict__ bias, float* __restrict__ Y, int Nrows){
    extern __shared__ float smbuf[];
    int m0 = blockIdx.x*128, n0 = blockIdx.y*64;
    int warp = threadIdx.x>>5, lane = threadIdx.x&31;
    int wm = warp>>1, wn = warp&1;
    float c[2][4][4] = {};
    gemm_pipe<true,true>(X + (size_t)m0*DH, DH, W + (size_t)n0*DH, DH, DH, c, smbuf, wm, wn, lane);
    int group = lane>>2, tq = lane&3;
    if (!TRANS){
        #pragma unroll
        for (int mi=0;mi<2;mi++)
        #pragma unroll
        for (int hh=0;hh<2;hh++)
        #pragma unroll
        for (int ni=0;ni<4;ni++)
        #pragma unroll
        for (int cc=0;cc<2;cc++){
            int row = m0 + wm*32 + mi*16 + group + hh*8;
            int col = n0 + wn*32 + ni*8 + tq*2 + cc;
            int b = row / Nrows, n = row - b*Nrows;
            int h = col >> 7, d = col & 127;
            Y[(((size_t)(b*HEADS + h)*Nrows + n) << 7) + d] = tf32r(c[mi][ni][hh*2+cc] + bias[col]);
        }
    } else {
        float* tr = smbuf;
        #pragma unroll
        for (int mi=0;mi<2;mi++)
        #pragma unroll
        for (int hh=0;hh<2;hh++)
        #pragma unroll
        for (int ni=0;ni<4;ni++)
        #pragma unroll
        for (int cc=0;cc<2;cc++){
            int rl = wm*32 + mi*16 + group + hh*8;
            int cl = wn*32 + ni*8 + tq*2 + cc;
            tr[cl*TRP + rl] = tf32r(c[mi][ni][hh*2+cc] + bias[n0+cl]);
        }
        __syncthreads();
        int b = m0 / Nrows, nloc0 = m0 - b*Nrows;
        int h = n0 >> 7, d0 = n0 & 127;
        float* Yt = Y + ((size_t)(b*HEADS + h)*DH + d0)*Nrows + nloc0;
        #pragma unroll
        for (int i = 0; i < 8; i++){
            int idx = threadIdx.x + i*256;   // 0..2047
            int cl = idx >> 5, q = idx & 31;
            *(float4*)&Yt[(size_t)cl*Nrows + q*4] = *(float4*)&tr[cl*TRP + q*4];
        }
    }
}

// ---------------- kernel 2: scores -> E, E^T, row/col sums ----------------
__global__ void __launch_bounds__(256)
scores_kernel(){
    extern __shared__ float smbuf[];
    __shared__ float srow[128], scol[64];
    int bh = blockIdx.z;
    int m0 = blockIdx.x*128, n0 = blockIdx.y*64;
    if (threadIdx.x < 128) srow[threadIdx.x] = 0.f;
    if (threadIdx.x < 64)  scol[threadIdx.x] = 0.f;
    const float* A = g_u + (size_t)bh*NQ*DH + (size_t)m0*DH;
    const float* B = g_v + (size_t)bh*NK*DH + (size_t)n0*DH;
    int warp = threadIdx.x>>5, lane = threadIdx.x&31;
    int wm = warp>>1, wn = warp&1;
    float c[2][4][4] = {};
    gemm_pipe<false,false>(A, DH, B, DH, DH, c, smbuf, wm, wn, lane);
    int group = lane>>2, tq = lane&3;
    float* Eg  = g_E  + (size_t)bh*NQ*NK;
    float* ETg = g_ET + (size_t)bh*NK*NQ;
    float* tr  = smbuf;
    float csum[8] = {0,0,0,0,0,0,0,0};
    #pragma unroll
    for (int mi=0;mi<2;mi++)
    #pragma unroll
    for (int hh=0;hh<2;hh++){
        int rl = wm*32 + mi*16 + group + hh*8;
        float rsum = 0.f;
        #pragma unroll
        for (int ni=0;ni<4;ni++)
        #pragma unroll
        for (int cc=0;cc<2;cc++){
            int cl = wn*32 + ni*8 + tq*2 + cc;
            float e = __expf(c[mi][ni][hh*2+cc] * SCALE);
            float er = tf32r(e);
            rsum += e;
            csum[ni*2+cc] += e;
            Eg[(size_t)(m0+rl)*NK + n0 + cl] = er;
            tr[cl*TRP + rl] = er;
        }
        atomicAdd(&srow[rl], rsum);
    }
    #pragma unroll
    for (int j = 0; j < 8; j++){
        int cl = wn*32 + (j>>1)*8 + tq*2 + (j&1);
        atomicAdd(&scol[cl], csum[j]);
    }
    __syncthreads();
    #pragma unroll
    for (int i = 0; i < 8; i++){
        int idx = threadIdx.x + i*256;
        int cl = idx >> 5, q = idx & 31;
        *(float4*)&ETg[(size_t)(n0+cl)*NQ + m0 + q*4] = *(float4*)&tr[cl*TRP + q*4];
    }
    if (threadIdx.x < 128) atomicAdd(&g_rowsum[bh*NQ + m0 + threadIdx.x], srow[threadIdx.x]);
    if (threadIdx.x < 64)  atomicAdd(&g_colsum[bh*NK + n0 + threadIdx.x], scol[threadIdx.x]);
}

// ---------------- kernel 3: attention-value GEMMs ----------------
// Mid[b, m, h, :] = (E_row / sum) @ Vt^T   — used for both P and D branches.
__global__ void __launch_bounds__(256)
av_kernel(const float* __restrict__ Ebase, const float* __restrict__ BT,
          const float* __restrict__ sums, float* __restrict__ Mid,
          int Lm, int Kd){
    extern __shared__ float smbuf[];
    int bh = blockIdx.z;
    int m0 = blockIdx.x*128, n0 = blockIdx.y*64;
    const float* A = Ebase + (size_t)bh*Lm*Kd + (size_t)m0*Kd;
    const float* B = BT + ((size_t)bh*DH + n0)*Kd;
    int warp = threadIdx.x>>5, lane = threadIdx.x&31;
    int wm = warp>>1, wn = warp&1;
    float c[2][4][4] = {};
    gemm_pipe<false,false>(A, Kd, B, Kd, Kd, c, smbuf, wm, wn, lane);
    int group = lane>>2, tq = lane&3;
    int b = bh >> 3, h = bh & 7;
    #pragma unroll
    for (int mi=0;mi<2;mi++)
    #pragma unroll
    for (int hh=0;hh<2;hh++){
        int row = m0 + wm*32 + mi*16 + group + hh*8;
        float inv = 1.0f / __ldg(&sums[(size_t)bh*Lm + row]);
        #pragma unroll
        for (int ni=0;ni<4;ni++)
        #pragma unroll
        for (int cc=0;cc<2;cc++){
            int col = n0 + wn*32 + ni*8 + tq*2 + cc;
            Mid[(((size_t)(b*Lm + row)*HEADS + h) << 7) + col] = tf32r(c[mi][ni][hh*2+cc] * inv);
        }
    }
}

// ---------------- kernel 4: output projection ----------------
// out[M,128] = X[M,1024] @ W[128,1024]^T + bias
__global__ void __launch_bounds__(256)
outproj_kernel(const float* __restrict__ X, const float* __restrict__ W,
               const float* __restrict__ bias, float* __restrict__ out){
    extern __shared__ float smbuf[];
    int m0 = blockIdx.x*128, n0 = blockIdx.y*64;
    int warp = threadIdx.x>>5, lane = threadIdx.x&31;
    int wm = warp>>1, wn = warp&1;
    float c[2][4][4] = {};
    gemm_pipe<false,true>(X + (size_t)m0*1024, 1024, W + (size_t)n0*1024, 1024, 1024, c, smbuf, wm, wn, lane);
    int group = lane>>2, tq = lane&3;
    #pragma unroll
    for (int mi=0;mi<2;mi++)
    #pragma unroll
    for (int hh=0;hh<2;hh++)
    #pragma unroll
    for (int ni=0;ni<4;ni++)
    #pragma unroll
    for (int cc=0;cc<2;cc++){
        int row = m0 + wm*32 + mi*16 + group + hh*8;
        int col = n0 + wn*32 + ni*8 + tq*2 + cc;
        out[((size_t)row << 7) + col] = c[mi][ni][hh*2+cc] + bias[col];
    }
}

// ---------------- launch ----------------
extern "C" void kernel_launch(void* const* d_in, const int* in_sizes, int n_in,
                              void* d_out, int out_size){
    const float* queries = (const float*)d_in[0];
    const float* keys    = (const float*)d_in[1];
    const float* Wq  = (const float*)d_in[2];
    const float* bq  = (const float*)d_in[3];
    const float* Wk  = (const float*)d_in[4];
    const float* bk  = (const float*)d_in[5];
    const float* Wp  = (const float*)d_in[6];
    const float* bp  = (const float*)d_in[7];
    const float* Wg  = (const float*)d_in[8];
    const float* bg  = (const float*)d_in[9];
    const float* Wo1 = (const float*)d_in[10];
    const float* bo1 = (const float*)d_in[11];
    const float* Wo2 = (const float*)d_in[12];
    const float* bo2 = (const float*)d_in[13];
    float* out = (float*)d_out;

    float *pu, *pv, *ppT, *pgT, *pE, *pET, *prs, *pcs, *pPmid, *pDmid;
    cudaGetSymbolAddress((void**)&pu,    g_u);
    cudaGetSymbolAddress((void**)&pv,    g_v);
    cudaGetSymbolAddress((void**)&ppT,   g_pT);
    cudaGetSymbolAddress((void**)&pgT,   g_gT);
    cudaGetSymbolAddress((void**)&pE,    g_E);
    cudaGetSymbolAddress((void**)&pET,   g_ET);
    cudaGetSymbolAddress((void**)&prs,   g_rowsum);
    cudaGetSymbolAddress((void**)&pcs,   g_colsum);
    cudaGetSymbolAddress((void**)&pPmid, g_Pmid);
    cudaGetSymbolAddress((void**)&pDmid, g_Dmid);

    cudaFuncSetAttribute(proj_kernel<false>, cudaFuncAttributeMaxDynamicSharedMemorySize, SMEM_BYTES);
    cudaFuncSetAttribute(proj_kernel<true>,  cudaFuncAttributeMaxDynamicSharedMemorySize, SMEM_BYTES);
    cudaFuncSetAttribute(scores_kernel,      cudaFuncAttributeMaxDynamicSharedMemorySize, SMEM_BYTES);
    cudaFuncSetAttribute(av_kernel,          cudaFuncAttributeMaxDynamicSharedMemorySize, SMEM_BYTES);
    cudaFuncSetAttribute(outproj_kernel,     cudaFuncAttributeMaxDynamicSharedMemorySize, SMEM_BYTES);

    cudaMemsetAsync(prs, 0, BH*NQ*sizeof(float));
    cudaMemsetAsync(pcs, 0, BH*NK*sizeof(float));

    // projections (u, v plain; p, g transposed)
    proj_kernel<false><<<dim3(64,16),  256, SMEM_BYTES>>>(queries, Wq, bq, pu,  NQ);
    proj_kernel<false><<<dim3(128,16), 256, SMEM_BYTES>>>(keys,    Wk, bk, pv,  NK);
    proj_kernel<true> <<<dim3(128,16), 256, SMEM_BYTES>>>(keys,    Wp, bp, ppT, NK);
    proj_kernel<true> <<<dim3(64,16),  256, SMEM_BYTES>>>(queries, Wg, bg, pgT, NQ);

    // scores -> E, E^T, sums
    scores_kernel<<<dim3(NQ/128, NK/64, BH), 256, SMEM_BYTES>>>();

    // attention-value GEMMs
    av_kernel<<<dim3(NQ/128, 2, BH), 256, SMEM_BYTES>>>(pE,  ppT, prs, pPmid, NQ, NK);
    av_kernel<<<dim3(NK/128, 2, BH), 256, SMEM_BYTES>>>(pET, pgT, pcs, pDmid, NK, NQ);

    // output projections
    outproj_kernel<<<dim3(BATCH*NQ/128, 2), 256, SMEM_BYTES>>>(pPmid, Wo1, bo1, out);
    outproj_kernel<<<dim3(BATCH*NK/128, 2), 256, SMEM_BYTES>>>(pDmid, Wo2, bo2, out + (size_t)BATCH*NQ*DH);
}

// round 3
// speedup vs baseline: 1.2155x; 1.0663x over previous
#include <cuda_runtime.h>
#include <cstdint>
#include <cstddef>

// ---------------- problem constants ----------------
#define BATCH 16
#define NQ    512
#define NK    1024
#define DH    128
#define HEADS 8
#define BH    (BATCH*HEADS)        // 128
#define SCALE 0.08838834764831845f // 1/sqrt(128)
#define SC2   0.12751741254364243f // SCALE * log2(e)

// ---------------- GEMM tiling (proj/outproj kernels) ----------------
#define BK   32
#define BKP  36
#define TRP  136
#define SMEM_FLOATS (2*128*BKP + 2*64*BKP)
#define SMEM_BYTES  (SMEM_FLOATS*4)

// ---------------- flash kernel smem layout (floats) ----------------
#define VSTR 144                  // 128 + 16 pad (mod 32 == 16 -> conflict-free LDS.128)
#define PSTR 48                   //  32 + 16 pad
#define FL_VB0 0
#define FL_VB1 (32*VSTR)          // 4608
#define FL_PB0 (2*32*VSTR)        // 9216
#define FL_PB1 (FL_PB0 + 128*PSTR) // 15360
#define FL_TOTAL (FL_PB1 + 128*PSTR) // 21504 floats = 86016 B

// ---------------- device scratch ----------------
__device__ float g_u  [(size_t)BH*NQ*DH];      // [bh][nq][dh]
__device__ float g_v  [(size_t)BH*NK*DH];      // [bh][nk][dh]
__device__ float g_pT [(size_t)BH*DH*NK];      // [bh][dh][nk]
__device__ float g_gT [(size_t)BH*DH*NQ];      // [bh][dh][nq]
__device__ float g_Pmid[(size_t)BATCH*NQ*HEADS*DH]; // [b,q,h,d]
__device__ float g_Dmid[(size_t)BATCH*NK*HEADS*DH]; // [b,k,h,d]

// ---------------- helpers ----------------
__device__ __forceinline__ float tf32r(float x){
    uint32_t u; asm("cvt.rna.tf32.f32 %0, %1;" : "=r"(u) : "f"(x));
    return __uint_as_float(u);
}

__device__ __forceinline__ void mma8(float (&c)[4], const uint32_t (&a)[4], const uint32_t (&b)[2]){
    asm volatile("mma.sync.aligned.m16n8k8.row.col.f32.tf32.tf32.f32 "
        "{%0,%1,%2,%3}, {%4,%5,%6,%7}, {%8,%9}, {%0,%1,%2,%3};"
        : "+f"(c[0]),"+f"(c[1]),"+f"(c[2]),"+f"(c[3])
        : "r"(a[0]),"r"(a[1]),"r"(a[2]),"r"(a[3]), "r"(b[0]),"r"(b[1]));
}

// ================= fused flash kernel =================
// For each bh, m-tile of 128 rows:
//   S[m][n]  = X[m][:] . Y[n][:]            (gemm1, K = 128)
//   E        = exp(S * SCALE)               (registers only)
//   acc[m][d] += E @ VT[d][:]^T             (gemm2, K = 32 per tile)
//   Mid[b][m][h][d] = acc / rowsum(E)
// Warp w owns rows w*16 .. w*16+15. One syncthreads per 32-key tile.
__global__ void __launch_bounds__(256)
flash_kernel(const float* __restrict__ X, const float* __restrict__ Y,
             const float* __restrict__ VT, float* __restrict__ Mid,
             int M, int Nk)
{
    extern __shared__ float sm[];
    const int bh = blockIdx.y;
    const int m0 = blockIdx.x * 128;
    const int tid = threadIdx.x, w = tid >> 5, lane = tid & 31;
    const int g = lane >> 2, tq = lane & 3;
    const float* Xb = X + ((size_t)bh*M + m0)*DH;
    const float* Yb = Y + (size_t)bh*Nk*DH;
    const float* Vb = VT + (size_t)bh*DH*Nk;

    // ---- stage X tile (128x128) into perm16 smem (transient, reuses buffers) ----
    #pragma unroll
    for (int it = 0; it < 4; it++){
        int c = tid + it*256;                 // 0..1023
        int r = c >> 3, blk = c & 7;
        const float* src = Xb + (size_t)r*DH + blk*16;
        float4 l0 = *(const float4*)(src);
        float4 l1 = *(const float4*)(src+4);
        float4 l2 = *(const float4*)(src+8);
        float4 l3 = *(const float4*)(src+12);
        float* d = sm + r*VSTR + blk*16;
        ((float4*)d)[0] = make_float4(l0.x, l1.x, l2.x, l3.x);
        ((float4*)d)[1] = make_float4(l0.y, l1.y, l2.y, l3.y);
        ((float4*)d)[2] = make_float4(l0.z, l1.z, l2.z, l3.z);
        ((float4*)d)[3] = make_float4(l0.w, l1.w, l2.w, l3.w);
    }
    __syncthreads();

    // ---- load A fragments for all 16 k-steps into registers ----
    uint32_t au[16][4];
    {
        const float* r0p = sm + (w*16 + g)*VSTR + 4*tq;
        const float* r8p = r0p + 8*VSTR;
        #pragma unroll
        for (int jp = 0; jp < 8; jp++){
            float4 f0 = *(const float4*)(r0p + jp*16);
            float4 f8 = *(const float4*)(r8p + jp*16);
            au[2*jp  ][0]=__float_as_uint(f0.x); au[2*jp  ][1]=__float_as_uint(f8.x);
            au[2*jp  ][2]=__float_as_uint(f0.y); au[2*jp  ][3]=__float_as_uint(f8.y);
            au[2*jp+1][0]=__float_as_uint(f0.z); au[2*jp+1][1]=__float_as_uint(f8.z);
            au[2*jp+1][2]=__float_as_uint(f0.w); au[2*jp+1][3]=__float_as_uint(f8.w);
        }
    }
    __syncthreads();   // staging area now dead

    // ---- loader coordinates ----
    const int vr = tid >> 3, vblk = tid & 7;   // v tile: 32 rows x 8 blocks of 16
    const int pr = tid >> 1, pblk = tid & 1;   // p tile: 128 rows x 2 blocks of 16
    const int NT = Nk / 32;

    // ---- prefetch tile 0 ----
    float4 rv0, rv1, rv2, rv3, rp0, rp1, rp2, rp3;
    {
        const float* sv = Yb + (size_t)vr*DH + vblk*16;
        rv0 = *(const float4*)(sv);   rv1 = *(const float4*)(sv+4);
        rv2 = *(const float4*)(sv+8); rv3 = *(const float4*)(sv+12);
        const float* sp = Vb + (size_t)pr*Nk + pblk*16;
        rp0 = *(const float4*)(sp);   rp1 = *(const float4*)(sp+4);
        rp2 = *(const float4*)(sp+8); rp3 = *(const float4*)(sp+12);
    }

    float acc[16][4] = {};
    float rs0 = 0.f, rs1 = 0.f;
    int buf = 0;

    for (int kt = 0; kt < NT; kt++){
        // store prefetched tiles into perm16 smem
        {
            float* d = sm + (buf ? FL_VB1 : FL_VB0) + vr*VSTR + vblk*16;
            ((float4*)d)[0] = make_float4(rv0.x, rv1.x, rv2.x, rv3.x);
            ((float4*)d)[1] = make_float4(rv0.y, rv1.y, rv2.y, rv3.y);
            ((float4*)d)[2] = make_float4(rv0.z, rv1.z, rv2.z, rv3.z);
            ((float4*)d)[3] = make_float4(rv0.w, rv1.w, rv2.w, rv3.w);
            float* dp = sm + (buf ? FL_PB1 : FL_PB0) + pr*PSTR + pblk*16;
            ((float4*)dp)[0] = make_float4(rp0.x, rp1.x, rp2.x, rp3.x);
            ((float4*)dp)[1] = make_float4(rp0.y, rp1.y, rp2.y, rp3.y);
            ((float4*)dp)[2] = make_float4(rp0.z, rp1.z, rp2.z, rp3.z);
            ((float4*)dp)[3] = make_float4(rp0.w, rp1.w, rp2.w, rp3.w);
        }
        __syncthreads();

        // prefetch next tile
        if (kt + 1 < NT){
            const float* sv = Yb + (size_t)((kt+1)*32 + vr)*DH + vblk*16;
            rv0 = *(const float4*)(sv);   rv1 = *(const float4*)(sv+4);
            rv2 = *(const float4*)(sv+8); rv3 = *(const float4*)(sv+12);
            const float* sp = Vb + (size_t)pr*Nk + (kt+1)*32 + pblk*16;
            rp0 = *(const float4*)(sp);   rp1 = *(const float4*)(sp+4);
            rp2 = *(const float4*)(sp+8); rp3 = *(const float4*)(sp+12);
        }

        // ---- gemm1: S[16 x 32] per warp, A in regs, B via LDS.128 ----
        float cs[4][4] = {};
        {
            const float* vbase = sm + (buf ? FL_VB1 : FL_VB0) + g*VSTR + 4*tq;
            #pragma unroll
            for (int jp = 0; jp < 8; jp++){
                #pragma unroll
                for (int ni = 0; ni < 4; ni++){
                    float4 f = *(const float4*)(vbase + ni*8*VSTR + jp*16);
                    uint32_t b0[2] = {__float_as_uint(f.x), __float_as_uint(f.y)};
                    uint32_t b1[2] = {__float_as_uint(f.z), __float_as_uint(f.w)};
                    mma8(cs[ni], au[2*jp],   b0);
                    mma8(cs[ni], au[2*jp+1], b1);
                }
            }
        }

        // ---- exp + rowsum + C-frag -> A-frag conversion (register shuffles) ----
        uint32_t ae[4][4];
        {
            const int s0 = (lane & ~3) | (tq >> 1);
            const int s1 = s0 + 2;
            const bool odd = tq & 1;
            #pragma unroll
            for (int ni = 0; ni < 4; ni++){
                float e0 = exp2f(cs[ni][0]*SC2), e1 = exp2f(cs[ni][1]*SC2);
                float e2 = exp2f(cs[ni][2]*SC2), e3 = exp2f(cs[ni][3]*SC2);
                rs0 += e0 + e1; rs1 += e2 + e3;
                e0 = tf32r(e0); e1 = tf32r(e1); e2 = tf32r(e2); e3 = tf32r(e3);
                float x0 = __shfl_sync(0xffffffffu, e0, s0);
                float x1 = __shfl_sync(0xffffffffu, e1, s0);
                float x2 = __shfl_sync(0xffffffffu, e2, s0);
                float x3 = __shfl_sync(0xffffffffu, e3, s0);
                float y0 = __shfl_sync(0xffffffffu, e0, s1);
                float y1 = __shfl_sync(0xffffffffu, e1, s1);
                float y2 = __shfl_sync(0xffffffffu, e2, s1);
                float y3 = __shfl_sync(0xffffffffu, e3, s1);
                ae[ni][0] = __float_as_uint(odd ? x1 : x0);
                ae[ni][1] = __float_as_uint(odd ? x3 : x2);
                ae[ni][2] = __float_as_uint(odd ? y1 : y0);
                ae[ni][3] = __float_as_uint(odd ? y3 : y2);
            }
        }

        // ---- gemm2: acc[16 x 128] per warp += E @ p-tile ----
        {
            const float* pbase = sm + (buf ? FL_PB1 : FL_PB0) + g*PSTR + 4*tq;
            #pragma unroll
            for (int jp = 0; jp < 2; jp++){
                #pragma unroll
                for (int n2 = 0; n2 < 16; n2++){
                    float4 f = *(const float4*)(pbase + n2*8*PSTR + jp*16);
                    uint32_t b0[2] = {__float_as_uint(f.x), __float_as_uint(f.y)};
                    uint32_t b1[2] = {__float_as_uint(f.z), __float_as_uint(f.w)};
                    mma8(acc[n2], ae[2*jp],   b0);
                    mma8(acc[n2], ae[2*jp+1], b1);
                }
            }
        }
        buf ^= 1;
    }

    // ---- normalize + store ----
    rs0 += __shfl_xor_sync(0xffffffffu, rs0, 1);
    rs0 += __shfl_xor_sync(0xffffffffu, rs0, 2);
    rs1 += __shfl_xor_sync(0xffffffffu, rs1, 1);
    rs1 += __shfl_xor_sync(0xffffffffu, rs1, 2);
    float i0 = 1.0f / rs0, i1 = 1.0f / rs1;
    int b = bh >> 3, h = bh & 7;
    int mg = m0 + w*16 + g;
    float* o0 = Mid + (((size_t)(b*M + mg    )*HEADS + h) << 7);
    float* o8 = Mid + (((size_t)(b*M + mg + 8)*HEADS + h) << 7);
    #pragma unroll
    for (int ni = 0; ni < 16; ni++){
        int col = ni*8 + 2*tq;
        *(float2*)(o0 + col) = make_float2(tf32r(acc[ni][0]*i0), tf32r(acc[ni][1]*i0));
        *(float2*)(o8 + col) = make_float2(tf32r(acc[ni][2]*i1), tf32r(acc[ni][3]*i1));
    }
}

// ================= proj / outproj (unchanged R2 core) =================
__device__ __forceinline__ void mma_slab(const float* As_w, const float* Bs_w,
                                         float (&c)[2][4][4], int lane){
    const int group = lane >> 2, tq = lane & 3;
    #pragma unroll
    for (int kk = 0; kk < BK; kk += 8) {
        uint32_t a[2][4], b[4][2];
        #pragma unroll
        for (int mi = 0; mi < 2; mi++){
            const float* ap = As_w + (mi*16 + group)*BKP + kk + tq;
            a[mi][0] = __float_as_uint(ap[0]);
            a[mi][1] = __float_as_uint(ap[8*BKP]);
            a[mi][2] = __float_as_uint(ap[4]);
            a[mi][3] = __float_as_uint(ap[8*BKP+4]);
        }
        #pragma unroll
        for (int ni = 0; ni < 4; ni++){
            const float* bp = Bs_w + (ni*8 + group)*BKP + kk + tq;
            b[ni][0] = __float_as_uint(bp[0]);
            b[ni][1] = __float_as_uint(bp[4]);
        }
        #pragma unroll
        for (int mi = 0; mi < 2; mi++)
            #pragma unroll
            for (int ni = 0; ni < 4; ni++)
                mma8(c[mi][ni], a[mi], b[ni]);
    }
}

template<bool CVTA, bool CVTB>
__device__ __forceinline__ void gemm_pipe(const float* __restrict__ A, int lda,
                                          const float* __restrict__ B, int ldb,
                                          int K, float (&c)[2][4][4],
                                          float* smbuf, int wm, int wn, int lane)
{
    const int fc = (threadIdx.x & 7) << 2;
    const int r0 = threadIdx.x >> 3;
    float4 ra[4], rb[2];
    #pragma unroll
    for (int i = 0; i < 4; i++) ra[i] = *(const float4*)(A + (size_t)(r0+32*i)*lda + fc);
    #pragma unroll
    for (int i = 0; i < 2; i++) rb[i] = *(const float4*)(B + (size_t)(r0+32*i)*ldb + fc);

    int buf = 0;
    for (int ks = BK;; ks += BK){
        float* As = smbuf + buf*(128*BKP);
        float* Bs = smbuf + 2*128*BKP + buf*(64*BKP);
        #pragma unroll
        for (int i = 0; i < 4; i++){
            float* d = &As[(r0+32*i)*BKP + fc];
            if (CVTA){ d[0]=tf32r(ra[i].x); d[1]=tf32r(ra[i].y); d[2]=tf32r(ra[i].z); d[3]=tf32r(ra[i].w); }
            else     { *(float4*)d = ra[i]; }
        }
        #pragma unroll
        for (int i = 0; i < 2; i++){
            float* d = &Bs[(r0+32*i)*BKP + fc];
            if (CVTB){ d[0]=tf32r(rb[i].x); d[1]=tf32r(rb[i].y); d[2]=tf32r(rb[i].z); d[3]=tf32r(rb[i].w); }
            else     { *(float4*)d = rb[i]; }
        }
        __syncthreads();
        if (ks < K){
            #pragma unroll
            for (int i = 0; i < 4; i++) ra[i] = *(const float4*)(A + ks + (size_t)(r0+32*i)*lda + fc);
            #pragma unroll
            for (int i = 0; i < 2; i++) rb[i] = *(const float4*)(B + ks + (size_t)(r0+32*i)*ldb + fc);
        }
        mma_slab(As + wm*32*BKP, Bs + wn*32*BKP, c, lane);
        if (ks >= K) break;
        buf ^= 1;
    }
    __syncthreads();
}

template<bool TRANS>
__global__ void __launch_bounds__(256)
proj_kernel(const float* __restrict__ X, const float* __restrict__ W,
            const float* __restrict__ bias, float* __restrict__ Y, int Nrows){
    extern __shared__ float smbuf[];
    int m0 = blockIdx.x*128, n0 = blockIdx.y*64;
    int warp = threadIdx.x>>5, lane = threadIdx.x&31;
    int wm = warp>>1, wn = warp&1;
    float c[2][4][4] = {};
    gemm_pipe<true,true>(X + (size_t)m0*DH, DH, W + (size_t)n0*DH, DH, DH, c, smbuf, wm, wn, lane);
    int group = lane>>2, tq = lane&3;
    if (!TRANS){
        #pragma unroll
        for (int mi=0;mi<2;mi++)
        #pragma unroll
        for (int hh=0;hh<2;hh++)
        #pragma unroll
        for (int ni=0;ni<4;ni++)
        #pragma unroll
        for (int cc=0;cc<2;cc++){
            int row = m0 + wm*32 + mi*16 + group + hh*8;
            int col = n0 + wn*32 + ni*8 + tq*2 + cc;
            int b = row / Nrows, n = row - b*Nrows;
            int h = col >> 7, d = col & 127;
            Y[(((size_t)(b*HEADS + h)*Nrows + n) << 7) + d] = tf32r(c[mi][ni][hh*2+cc] + bias[col]);
        }
    } else {
        float* tr = smbuf;
        #pragma unroll
        for (int mi=0;mi<2;mi++)
        #pragma unroll
        for (int hh=0;hh<2;hh++)
        #pragma unroll
        for (int ni=0;ni<4;ni++)
        #pragma unroll
        for (int cc=0;cc<2;cc++){
            int rl = wm*32 + mi*16 + group + hh*8;
            int cl = wn*32 + ni*8 + tq*2 + cc;
            tr[cl*TRP + rl] = tf32r(c[mi][ni][hh*2+cc] + bias[n0+cl]);
        }
        __syncthreads();
        int b = m0 / Nrows, nloc0 = m0 - b*Nrows;
        int h = n0 >> 7, d0 = n0 & 127;
        float* Yt = Y + ((size_t)(b*HEADS + h)*DH + d0)*Nrows + nloc0;
        #pragma unroll
        for (int i = 0; i < 8; i++){
            int idx = threadIdx.x + i*256;
            int cl = idx >> 5, q = idx & 31;
            *(float4*)&Yt[(size_t)cl*Nrows + q*4] = *(float4*)&tr[cl*TRP + q*4];
        }
    }
}

__global__ void __launch_bounds__(256)
outproj_kernel(const float* __restrict__ X, const float* __restrict__ W,
               const float* __restrict__ bias, float* __restrict__ out){
    extern __shared__ float smbuf[];
    int m0 = blockIdx.x*128, n0 = blockIdx.y*64;
    int warp = threadIdx.x>>5, lane = threadIdx.x&31;
    int wm = warp>>1, wn = warp&1;
    float c[2][4][4] = {};
    gemm_pipe<false,true>(X + (size_t)m0*1024, 1024, W + (size_t)n0*1024, 1024, 1024, c, smbuf, wm, wn, lane);
    int group = lane>>2, tq = lane&3;
    #pragma unroll
    for (int mi=0;mi<2;mi++)
    #pragma unroll
    for (int hh=0;hh<2;hh++)
    #pragma unroll
    for (int ni=0;ni<4;ni++)
    #pragma unroll
    for (int cc=0;cc<2;cc++){
        int row = m0 + wm*32 + mi*16 + group + hh*8;
        int col = n0 + wn*32 + ni*8 + tq*2 + cc;
        out[((size_t)row << 7) + col] = c[mi][ni][hh*2+cc] + bias[col];
    }
}

// ---------------- launch ----------------
extern "C" void kernel_launch(void* const* d_in, const int* in_sizes, int n_in,
                              void* d_out, int out_size){
    const float* queries = (const float*)d_in[0];
    const float* keys    = (const float*)d_in[1];
    const float* Wq  = (const float*)d_in[2];
    const float* bq  = (const float*)d_in[3];
    const float* Wk  = (const float*)d_in[4];
    const float* bk  = (const float*)d_in[5];
    const float* Wp  = (const float*)d_in[6];
    const float* bp  = (const float*)d_in[7];
    const float* Wg  = (const float*)d_in[8];
    const float* bg  = (const float*)d_in[9];
    const float* Wo1 = (const float*)d_in[10];
    const float* bo1 = (const float*)d_in[11];
    const float* Wo2 = (const float*)d_in[12];
    const float* bo2 = (const float*)d_in[13];
    float* out = (float*)d_out;

    float *pu, *pv, *ppT, *pgT, *pPmid, *pDmid;
    cudaGetSymbolAddress((void**)&pu,    g_u);
    cudaGetSymbolAddress((void**)&pv,    g_v);
    cudaGetSymbolAddress((void**)&ppT,   g_pT);
    cudaGetSymbolAddress((void**)&pgT,   g_gT);
    cudaGetSymbolAddress((void**)&pPmid, g_Pmid);
    cudaGetSymbolAddress((void**)&pDmid, g_Dmid);

    cudaFuncSetAttribute(proj_kernel<false>, cudaFuncAttributeMaxDynamicSharedMemorySize, SMEM_BYTES);
    cudaFuncSetAttribute(proj_kernel<true>,  cudaFuncAttributeMaxDynamicSharedMemorySize, SMEM_BYTES);
    cudaFuncSetAttribute(outproj_kernel,     cudaFuncAttributeMaxDynamicSharedMemorySize, SMEM_BYTES);
    cudaFuncSetAttribute(flash_kernel,       cudaFuncAttributeMaxDynamicSharedMemorySize, FL_TOTAL*4);

    // projections (u, v plain; p, g transposed)
    proj_kernel<false><<<dim3(64,16),  256, SMEM_BYTES>>>(queries, Wq, bq, pu,  NQ);
    proj_kernel<false><<<dim3(128,16), 256, SMEM_BYTES>>>(keys,    Wk, bk, pv,  NK);
    proj_kernel<true> <<<dim3(128,16), 256, SMEM_BYTES>>>(keys,    Wp, bp, ppT, NK);
    proj_kernel<true> <<<dim3(64,16),  256, SMEM_BYTES>>>(queries, Wg, bg, pgT, NQ);

    // fused attention branches
    flash_kernel<<<dim3(NQ/128, BH), 256, FL_TOTAL*4>>>(pu, pv, ppT, pPmid, NQ, NK);
    flash_kernel<<<dim3(NK/128, BH), 256, FL_TOTAL*4>>>(pv, pu, pgT, pDmid, NK, NQ);

    // output projections
    outproj_kernel<<<dim3(BATCH*NQ/128, 2), 256, SMEM_BYTES>>>(pPmid, Wo1, bo1, out);
    outproj_kernel<<<dim3(BATCH*NK/128, 2), 256, SMEM_BYTES>>>(pDmid, Wo2, bo2, out + (size_t)BATCH*NQ*DH);
}

// round 4
// speedup vs baseline: 2.1787x; 1.7925x over previous
#include <cuda_runtime.h>
#include <cuda_fp16.h>
#include <cstdint>
#include <cstddef>

// ---------------- problem constants ----------------
#define BATCH 16
#define NQ    512
#define NK    1024
#define DH    128
#define HEADS 8
#define BH    (BATCH*HEADS)        // 128
#define SC2   0.12751741254364243f // (1/sqrt(128)) * log2(e)

// ---------------- proj/outproj tiling ----------------
#define BK   32
#define BKP  36
#define TRP  136
#define SMEM_FLOATS (2*128*BKP + 2*64*BKP)
#define SMEM_BYTES  (SMEM_FLOATS*4)

// ---------------- flash smem layout (uint32 words) ----------------
#define XSTR 80
#define FL_XS  0
#define FL_VB0 (128*XSTR)          // 10240
#define FL_VB1 (FL_VB0 + 32*80)    // 12800
#define FL_PB0 (FL_VB1 + 32*80)    // 15360
#define FL_PB1 (FL_PB0 + 128*16)   // 17408
#define FL_WORDS (FL_PB1 + 128*16) // 19456
#define FL_BYTES (FL_WORDS*4)      // 77824

// ---------------- device scratch (fp16, perm32 layout along K dim) ----------------
__device__ __half g_u  [(size_t)BH*NQ*DH];
__device__ __half g_v  [(size_t)BH*NK*DH];
__device__ __half g_pT [(size_t)BH*DH*NK];
__device__ __half g_gT [(size_t)BH*DH*NQ];
__device__ __half g_Pmid[(size_t)BATCH*NQ*HEADS*DH]; // plain [b,q,h,d]
__device__ __half g_Dmid[(size_t)BATCH*NK*HEADS*DH];

// ---------------- helpers ----------------
__device__ __forceinline__ float tf32r(float x){
    uint32_t u; asm("cvt.rna.tf32.f32 %0, %1;" : "=r"(u) : "f"(x));
    return __uint_as_float(u);
}
__device__ __forceinline__ uint32_t packh2(float a, float b){
    __half2 h = __floats2half2_rn(a, b);
    return *reinterpret_cast<uint32_t*>(&h);
}
__device__ __forceinline__ void mma8(float (&c)[4], const uint32_t (&a)[4], const uint32_t (&b)[2]){
    asm volatile("mma.sync.aligned.m16n8k8.row.col.f32.tf32.tf32.f32 "
        "{%0,%1,%2,%3}, {%4,%5,%6,%7}, {%8,%9}, {%0,%1,%2,%3};"
        : "+f"(c[0]),"+f"(c[1]),"+f"(c[2]),"+f"(c[3])
        : "r"(a[0]),"r"(a[1]),"r"(a[2]),"r"(a[3]), "r"(b[0]),"r"(b[1]));
}
__device__ __forceinline__ void mma16h(float (&c)[4], uint32_t a0, uint32_t a1, uint32_t a2, uint32_t a3,
                                       uint32_t b0, uint32_t b1){
    asm volatile("mma.sync.aligned.m16n8k16.row.col.f32.f16.f16.f32 "
        "{%0,%1,%2,%3}, {%4,%5,%6,%7}, {%8,%9}, {%0,%1,%2,%3};"
        : "+f"(c[0]),"+f"(c[1]),"+f"(c[2]),"+f"(c[3])
        : "r"(a0),"r"(a1),"r"(a2),"r"(a3), "r"(b0),"r"(b1));
}
__device__ __forceinline__ void cpa16(uint32_t dst_shared, const void* src){
    asm volatile("cp.async.cg.shared.global [%0], [%1], 16;" :: "r"(dst_shared), "l"(src));
}
__device__ __forceinline__ void cpa_commit(){ asm volatile("cp.async.commit_group;"); }
__device__ __forceinline__ void cpa_wait0(){ asm volatile("cp.async.wait_group 0;"); }

// perm32 word index within a 32-half chunk: halves (s*16+hi*8+2j, +1) live at word j*4+hi*2+s
__device__ __forceinline__ int perm_w(int h32){        // h32 = even half index 0..30
    int s = (h32 >> 4) & 1, hi = (h32 >> 3) & 1, j = (h32 & 7) >> 1;
    return j*4 + hi*2 + s;
}

// ================= fused flash kernel (fp16) =================
// acc[m][d] = sum_k exp(scale * X[m]·Y[k]) * VT[d][k]  / rowsum
__global__ void __launch_bounds__(256, 2)
flash_kernel(const __half* __restrict__ X, const __half* __restrict__ Y,
             const __half* __restrict__ VT, __half* __restrict__ Mid,
             int M, int Nk)
{
    extern __shared__ uint32_t smw[];
    const int bh = blockIdx.y;
    const int m0 = blockIdx.x * 128;
    const int tid = threadIdx.x, w = tid >> 5, lane = tid & 31;
    const int g = lane >> 2, tq = lane & 3;
    const int Nk2 = Nk >> 1;
    const uint32_t* Xw = (const uint32_t*)(X + ((size_t)bh*M + m0)*DH);
    const uint32_t* Yw = (const uint32_t*)(Y + (size_t)bh*Nk*DH);
    const uint32_t* Vw = (const uint32_t*)(VT + (size_t)bh*DH*Nk);

    // ---- stage X tile (128 rows x 64 words) into XS (stride 80) ----
    #pragma unroll
    for (int i = 0; i < 8; i++){
        int u = tid + i*256;                // 0..2047
        int r = u >> 4, wq = u & 15;
        *(uint4*)(smw + FL_XS + r*XSTR + wq*4) = *(const uint4*)(Xw + (size_t)r*64 + wq*4);
    }
    __syncthreads();

    // ---- issue tile 0 ----
    const int NT = Nk / 32;
    uint32_t smbase = (uint32_t)__cvta_generic_to_shared(smw);
    {
        #pragma unroll
        for (int i = 0; i < 2; i++){
            int u = tid + i*256;
            int r = u >> 4, wq = u & 15;
            cpa16(smbase + (FL_VB0 + r*80 + wq*4)*4, Yw + (size_t)r*64 + wq*4);
        }
        #pragma unroll
        for (int i = 0; i < 2; i++){
            int u = tid + i*256;
            int r = u >> 2, wq = u & 3;
            cpa16(smbase + (FL_PB0 + r*16 + wq*4)*4, Vw + (size_t)r*Nk2 + wq*4);
        }
        cpa_commit();
    }

    float acc[16][4] = {};
    float rs0 = 0.f, rs1 = 0.f;
    int buf = 0;

    for (int kt = 0; kt < NT; kt++){
        cpa_wait0();
        __syncthreads();

        // issue next tile into other buffer
        if (kt + 1 < NT){
            int vb = buf ? FL_VB0 : FL_VB1;
            int pb = buf ? FL_PB0 : FL_PB1;
            #pragma unroll
            for (int i = 0; i < 2; i++){
                int u = tid + i*256;
                int r = u >> 4, wq = u & 15;
                cpa16(smbase + (vb + r*80 + wq*4)*4, Yw + (size_t)((kt+1)*32 + r)*64 + wq*4);
            }
            #pragma unroll
            for (int i = 0; i < 2; i++){
                int u = tid + i*256;
                int r = u >> 2, wq = u & 3;
                cpa16(smbase + (pb + r*16 + wq*4)*4, Vw + (size_t)r*Nk2 + (kt+1)*16 + wq*4);
            }
            cpa_commit();
        }

        const int vb = buf ? FL_VB1 : FL_VB0;
        const int pb = buf ? FL_PB1 : FL_PB0;

        // ---- gemm1: S[16 x 32] per warp ----
        float cs[4][4] = {};
        #pragma unroll
        for (int kk2 = 0; kk2 < 4; kk2++){
            uint4 xa = *(const uint4*)(smw + FL_XS + (w*16 + g)*XSTR + kk2*16 + tq*4);
            uint4 xb = *(const uint4*)(smw + FL_XS + (w*16 + g + 8)*XSTR + kk2*16 + tq*4);
            #pragma unroll
            for (int ni = 0; ni < 4; ni++){
                uint4 r = *(const uint4*)(smw + vb + (ni*8 + g)*80 + kk2*16 + tq*4);
                mma16h(cs[ni], xa.x, xb.x, xa.z, xb.z, r.x, r.z);
                mma16h(cs[ni], xa.y, xb.y, xa.w, xb.w, r.y, r.w);
            }
        }

        // ---- exp + rowsum + pack to fp16 A-fragments (no shuffles) ----
        uint32_t eh[4][2];
        #pragma unroll
        for (int ni = 0; ni < 4; ni++){
            float e0 = exp2f(cs[ni][0]*SC2), e1 = exp2f(cs[ni][1]*SC2);
            float e2 = exp2f(cs[ni][2]*SC2), e3 = exp2f(cs[ni][3]*SC2);
            rs0 += e0 + e1; rs1 += e2 + e3;
            eh[ni][0] = packh2(e0, e1);
            eh[ni][1] = packh2(e2, e3);
        }

        // ---- gemm2: acc[16 x 128] per warp += E @ Ptile ----
        #pragma unroll
        for (int n2 = 0; n2 < 16; n2++){
            uint4 r = *(const uint4*)(smw + pb + (n2*8 + g)*16 + tq*4);
            mma16h(acc[n2], eh[0][0], eh[0][1], eh[1][0], eh[1][1], r.x, r.z);
            mma16h(acc[n2], eh[2][0], eh[2][1], eh[3][0], eh[3][1], r.y, r.w);
        }
        buf ^= 1;
    }

    // ---- normalize + store (fp16) ----
    rs0 += __shfl_xor_sync(0xffffffffu, rs0, 1);
    rs0 += __shfl_xor_sync(0xffffffffu, rs0, 2);
    rs1 += __shfl_xor_sync(0xffffffffu, rs1, 1);
    rs1 += __shfl_xor_sync(0xffffffffu, rs1, 2);
    float i0 = 1.0f / rs0, i1 = 1.0f / rs1;
    int b = bh >> 3, h = bh & 7;
    int mg = m0 + w*16 + g;
    __half* o0 = Mid + (((size_t)(b*M + mg    )*HEADS + h) << 7);
    __half* o8 = Mid + (((size_t)(b*M + mg + 8)*HEADS + h) << 7);
    #pragma unroll
    for (int n2 = 0; n2 < 16; n2++){
        int col = n2*8 + 2*tq;
        *(__half2*)(o0 + col) = __floats2half2_rn(acc[n2][0]*i0, acc[n2][1]*i0);
        *(__half2*)(o8 + col) = __floats2half2_rn(acc[n2][2]*i1, acc[n2][3]*i1);
    }
}

// ================= tf32 GEMM core for projections =================
__device__ __forceinline__ void mma_slab(const float* As_w, const float* Bs_w,
                                         float (&c)[2][4][4], int lane){
    const int group = lane >> 2, tq = lane & 3;
    #pragma unroll
    for (int kk = 0; kk < BK; kk += 8) {
        uint32_t a[2][4], b[4][2];
        #pragma unroll
        for (int mi = 0; mi < 2; mi++){
            const float* ap = As_w + (mi*16 + group)*BKP + kk + tq;
            a[mi][0] = __float_as_uint(ap[0]);
            a[mi][1] = __float_as_uint(ap[8*BKP]);
            a[mi][2] = __float_as_uint(ap[4]);
            a[mi][3] = __float_as_uint(ap[8*BKP+4]);
        }
        #pragma unroll
        for (int ni = 0; ni < 4; ni++){
            const float* bp = Bs_w + (ni*8 + group)*BKP + kk + tq;
            b[ni][0] = __float_as_uint(bp[0]);
            b[ni][1] = __float_as_uint(bp[4]);
        }
        #pragma unroll
        for (int mi = 0; mi < 2; mi++)
            #pragma unroll
            for (int ni = 0; ni < 4; ni++)
                mma8(c[mi][ni], a[mi], b[ni]);
    }
}

__device__ __forceinline__ void gemm_pipe_ff(const float* __restrict__ A, int lda,
                                             const float* __restrict__ B, int ldb,
                                             int K, float (&c)[2][4][4],
                                             float* smbuf, int wm, int wn, int lane)
{
    const int fc = (threadIdx.x & 7) << 2;
    const int r0 = threadIdx.x >> 3;
    float4 ra[4], rb[2];
    #pragma unroll
    for (int i = 0; i < 4; i++) ra[i] = *(const float4*)(A + (size_t)(r0+32*i)*lda + fc);
    #pragma unroll
    for (int i = 0; i < 2; i++) rb[i] = *(const float4*)(B + (size_t)(r0+32*i)*ldb + fc);

    int buf = 0;
    for (int ks = BK;; ks += BK){
        float* As = smbuf + buf*(128*BKP);
        float* Bs = smbuf + 2*128*BKP + buf*(64*BKP);
        #pragma unroll
        for (int i = 0; i < 4; i++){
            float* d = &As[(r0+32*i)*BKP + fc];
            d[0]=tf32r(ra[i].x); d[1]=tf32r(ra[i].y); d[2]=tf32r(ra[i].z); d[3]=tf32r(ra[i].w);
        }
        #pragma unroll
        for (int i = 0; i < 2; i++){
            float* d = &Bs[(r0+32*i)*BKP + fc];
            d[0]=tf32r(rb[i].x); d[1]=tf32r(rb[i].y); d[2]=tf32r(rb[i].z); d[3]=tf32r(rb[i].w);
        }
        __syncthreads();
        if (ks < K){
            #pragma unroll
            for (int i = 0; i < 4; i++) ra[i] = *(const float4*)(A + ks + (size_t)(r0+32*i)*lda + fc);
            #pragma unroll
            for (int i = 0; i < 2; i++) rb[i] = *(const float4*)(B + ks + (size_t)(r0+32*i)*ldb + fc);
        }
        mma_slab(As + wm*32*BKP, Bs + wn*32*BKP, c, lane);
        if (ks >= K) break;
        buf ^= 1;
    }
    __syncthreads();
}

// ---------------- input projections -> fp16 perm32 scratch ----------------
template<bool TRANS>
__global__ void __launch_bounds__(256)
proj_kernel(const float* __restrict__ X, const float* __restrict__ W,
            const float* __restrict__ bias, __half* __restrict__ Y, int Nrows){
    extern __shared__ float smbuf[];
    int m0 = blockIdx.x*128, n0 = blockIdx.y*64;
    int warp = threadIdx.x>>5, lane = threadIdx.x&31;
    int wm = warp>>1, wn = warp&1;
    float c[2][4][4] = {};
    gemm_pipe_ff(X + (size_t)m0*DH, DH, W + (size_t)n0*DH, DH, DH, c, smbuf, wm, wn, lane);
    int group = lane>>2, tq = lane&3;
    if (!TRANS){
        __half2* Y2 = (__half2*)Y;
        #pragma unroll
        for (int mi=0;mi<2;mi++)
        #pragma unroll
        for (int hh=0;hh<2;hh++)
        #pragma unroll
        for (int ni=0;ni<4;ni++){
            int row = m0 + wm*32 + mi*16 + group + hh*8;
            int cg  = n0 + wn*32 + ni*8 + tq*2;
            int b = row / Nrows, n = row - b*Nrows;
            int h = cg >> 7, d = cg & 127;
            int wrd = (d >> 5)*16 + perm_w(d & 31);
            Y2[(size_t)((b*HEADS + h)*Nrows + n)*64 + wrd] =
                __floats2half2_rn(c[mi][ni][hh*2] + bias[cg], c[mi][ni][hh*2+1] + bias[cg+1]);
        }
    } else {
        float* tr = smbuf;
        #pragma unroll
        for (int mi=0;mi<2;mi++)
        #pragma unroll
        for (int hh=0;hh<2;hh++)
        #pragma unroll
        for (int ni=0;ni<4;ni++)
        #pragma unroll
        for (int cc=0;cc<2;cc++){
            int rl = wm*32 + mi*16 + group + hh*8;
            int cl = wn*32 + ni*8 + tq*2 + cc;
            tr[cl*TRP + rl] = c[mi][ni][hh*2+cc] + bias[n0+cl];
        }
        __syncthreads();
        // permuted fp16 writer: 64 cols x 4 chunks of 32 m-halves
        int b = m0 / Nrows, nloc0 = m0 - b*Nrows;
        int h = n0 >> 7, d0 = n0 & 127;
        int cl = threadIdx.x >> 2, cch = threadIdx.x & 3;
        const float* src = tr + cl*TRP + cch*32;
        uint32_t wds[16];
        #pragma unroll
        for (int wd = 0; wd < 16; wd++){
            int j = wd >> 2, hi = (wd >> 1) & 1, s = wd & 1;
            int h0 = s*16 + hi*8 + 2*j;
            wds[wd] = packh2(src[h0], src[h0+1]);
        }
        uint32_t* Yw = (uint32_t*)Y;
        uint32_t* dst = Yw + ((size_t)(b*HEADS + h)*DH + d0 + cl)*(size_t)(Nrows>>1) + (nloc0>>1) + cch*16;
        #pragma unroll
        for (int q = 0; q < 4; q++)
            ((uint4*)dst)[q] = make_uint4(wds[q*4], wds[q*4+1], wds[q*4+2], wds[q*4+3]);
    }
}

// ---------------- output projection: fp16 A, fp32 W ----------------
__global__ void __launch_bounds__(256)
outproj_kernel(const __half* __restrict__ X, const float* __restrict__ W,
               const float* __restrict__ bias, float* __restrict__ out){
    extern __shared__ float smbuf[];
    int m0 = blockIdx.x*128, n0 = blockIdx.y*64;
    int warp = threadIdx.x>>5, lane = threadIdx.x&31;
    int wm = warp>>1, wn = warp&1;
    const __half* A = X + (size_t)m0*1024;
    const float*  B = W + (size_t)n0*1024;

    const int fcA = (threadIdx.x & 3) << 3;   // 8 halves
    const int rA  = threadIdx.x >> 2;         // 0..63
    const int fcB = (threadIdx.x & 7) << 2;
    const int rB  = threadIdx.x >> 3;

    float c[2][4][4] = {};
    uint4  ra[2]; float4 rb[2];
    #pragma unroll
    for (int i = 0; i < 2; i++) ra[i] = *(const uint4*)(A + (size_t)(rA+64*i)*1024 + fcA);
    #pragma unroll
    for (int i = 0; i < 2; i++) rb[i] = *(const float4*)(B + (size_t)(rB+32*i)*1024 + fcB);

    int buf = 0;
    for (int ks = BK;; ks += BK){
        float* As = smbuf + buf*(128*BKP);
        float* Bs = smbuf + 2*128*BKP + buf*(64*BKP);
        #pragma unroll
        for (int i = 0; i < 2; i++){
            float* d = &As[(rA+64*i)*BKP + fcA];
            uint32_t wsv[4] = {ra[i].x, ra[i].y, ra[i].z, ra[i].w};
            #pragma unroll
            for (int j = 0; j < 4; j++){
                __half2 hh2 = *reinterpret_cast<__half2*>(&wsv[j]);
                d[2*j]   = __low2float(hh2);
                d[2*j+1] = __high2float(hh2);
            }
        }
        #pragma unroll
        for (int i = 0; i < 2; i++){
            float* d = &Bs[(rB+32*i)*BKP + fcB];
            d[0]=tf32r(rb[i].x); d[1]=tf32r(rb[i].y); d[2]=tf32r(rb[i].z); d[3]=tf32r(rb[i].w);
        }
        __syncthreads();
        if (ks < 1024){
            #pragma unroll
            for (int i = 0; i < 2; i++) ra[i] = *(const uint4*)(A + ks + (size_t)(rA+64*i)*1024 + fcA);
            #pragma unroll
            for (int i = 0; i < 2; i++) rb[i] = *(const float4*)(B + ks + (size_t)(rB+32*i)*1024 + fcB);
        }
        mma_slab(As + wm*32*BKP, Bs + wn*32*BKP, c, lane);
        if (ks >= 1024) break;
        buf ^= 1;
    }

    int group = lane>>2, tq = lane&3;
    #pragma unroll
    for (int mi=0;mi<2;mi++)
    #pragma unroll
    for (int hh=0;hh<2;hh++)
    #pragma unroll
    for (int ni=0;ni<4;ni++)
    #pragma unroll
    for (int cc=0;cc<2;cc++){
        int row = m0 + wm*32 + mi*16 + group + hh*8;
        int col = n0 + wn*32 + ni*8 + tq*2 + cc;
        out[((size_t)row << 7) + col] = c[mi][ni][hh*2+cc] + bias[col];
    }
}

// ---------------- launch ----------------
extern "C" void kernel_launch(void* const* d_in, const int* in_sizes, int n_in,
                              void* d_out, int out_size){
    const float* queries = (const float*)d_in[0];
    const float* keys    = (const float*)d_in[1];
    const float* Wq  = (const float*)d_in[2];
    const float* bq  = (const float*)d_in[3];
    const float* Wk  = (const float*)d_in[4];
    const float* bk  = (const float*)d_in[5];
    const float* Wp  = (const float*)d_in[6];
    const float* bp  = (const float*)d_in[7];
    const float* Wg  = (const float*)d_in[8];
    const float* bg  = (const float*)d_in[9];
    const float* Wo1 = (const float*)d_in[10];
    const float* bo1 = (const float*)d_in[11];
    const float* Wo2 = (const float*)d_in[12];
    const float* bo2 = (const float*)d_in[13];
    float* out = (float*)d_out;

    __half *pu, *pv, *ppT, *pgT, *pPmid, *pDmid;
    cudaGetSymbolAddress((void**)&pu,    g_u);
    cudaGetSymbolAddress((void**)&pv,    g_v);
    cudaGetSymbolAddress((void**)&ppT,   g_pT);
    cudaGetSymbolAddress((void**)&pgT,   g_gT);
    cudaGetSymbolAddress((void**)&pPmid, g_Pmid);
    cudaGetSymbolAddress((void**)&pDmid, g_Dmid);

    cudaFuncSetAttribute(proj_kernel<false>, cudaFuncAttributeMaxDynamicSharedMemorySize, SMEM_BYTES);
    cudaFuncSetAttribute(proj_kernel<true>,  cudaFuncAttributeMaxDynamicSharedMemorySize, SMEM_BYTES);
    cudaFuncSetAttribute(outproj_kernel,     cudaFuncAttributeMaxDynamicSharedMemorySize, SMEM_BYTES);
    cudaFuncSetAttribute(flash_kernel,       cudaFuncAttributeMaxDynamicSharedMemorySize, FL_BYTES);

    // projections (u, v plain perm32; p, g transposed perm32)
    proj_kernel<false><<<dim3(64,16),  256, SMEM_BYTES>>>(queries, Wq, bq, pu,  NQ);
    proj_kernel<false><<<dim3(128,16), 256, SMEM_BYTES>>>(keys,    Wk, bk, pv,  NK);
    proj_kernel<true> <<<dim3(128,16), 256, SMEM_BYTES>>>(keys,    Wp, bp, ppT, NK);
    proj_kernel<true> <<<dim3(64,16),  256, SMEM_BYTES>>>(queries, Wg, bg, pgT, NQ);

    // fused attention branches
    flash_kernel<<<dim3(NQ/128, BH), 256, FL_BYTES>>>(pu, pv, ppT, pPmid, NQ, NK);
    flash_kernel<<<dim3(NK/128, BH), 256, FL_BYTES>>>(pv, pu, pgT, pDmid, NK, NQ);

    // output projections
    outproj_kernel<<<dim3(BATCH*NQ/128, 2), 256, SMEM_BYTES>>>(pPmid, Wo1, bo1, out);
    outproj_kernel<<<dim3(BATCH*NK/128, 2), 256, SMEM_BYTES>>>(pDmid, Wo2, bo2, out + (size_t)BATCH*NQ*DH);
}

// round 5
// speedup vs baseline: 2.2845x; 1.0486x over previous
#include <cuda_runtime.h>
#include <cuda_fp16.h>
#include <cstdint>
#include <cstddef>

// ---------------- problem constants ----------------
#define BATCH 16
#define NQ    512
#define NK    1024
#define DH    128
#define HEADS 8
#define BH    (BATCH*HEADS)        // 128
#define SC2   0.12751741254364243f // (1/sqrt(128)) * log2(e)

// ---------------- flash smem layout (uint32 words) ----------------
#define XSTR 80
#define FL_XS  0
#define FL_VB0 (128*XSTR)          // 10240
#define FL_VB1 (FL_VB0 + 32*80)    // 12800
#define FL_PB0 (FL_VB1 + 32*80)    // 15360
#define FL_PB1 (FL_PB0 + 128*16)   // 17408
#define FL_WORDS (FL_PB1 + 128*16) // 19456
#define FL_BYTES (FL_WORDS*4)      // 77824

// ---------------- proj smem: stage 128x80 + 64x80 words ----------------
#define PRJ_WORDS (128*80 + 64*80) // 15360 words = 61440 B
#define TRP 136                    // fp32 transpose staging stride

// ---------------- device scratch (fp16, perm32 along K dim) ----------------
__device__ __half g_u  [(size_t)BH*NQ*DH];
__device__ __half g_v  [(size_t)BH*NK*DH];
__device__ __half g_pT [(size_t)BH*DH*NK];
__device__ __half g_gT [(size_t)BH*DH*NQ];
__device__ __half g_Pmid[(size_t)BATCH*NQ*HEADS*DH]; // [b*NQ+q][1024] perm32
__device__ __half g_Dmid[(size_t)BATCH*NK*HEADS*DH];
__device__ __half g_Wo1h[128*1024];                  // [n][1024] perm32
__device__ __half g_Wo2h[128*1024];

// ---------------- helpers ----------------
__device__ __forceinline__ uint32_t packh2(float a, float b){
    __half2 h = __floats2half2_rn(a, b);
    return *reinterpret_cast<uint32_t*>(&h);
}
__device__ __forceinline__ void mma16h(float (&c)[4], uint32_t a0, uint32_t a1, uint32_t a2, uint32_t a3,
                                       uint32_t b0, uint32_t b1){
    asm volatile("mma.sync.aligned.m16n8k16.row.col.f32.f16.f16.f32 "
        "{%0,%1,%2,%3}, {%4,%5,%6,%7}, {%8,%9}, {%0,%1,%2,%3};"
        : "+f"(c[0]),"+f"(c[1]),"+f"(c[2]),"+f"(c[3])
        : "r"(a0),"r"(a1),"r"(a2),"r"(a3), "r"(b0),"r"(b1));
}
__device__ __forceinline__ void cpa16(uint32_t dst_shared, const void* src){
    asm volatile("cp.async.cg.shared.global [%0], [%1], 16;" :: "r"(dst_shared), "l"(src));
}
__device__ __forceinline__ void cpa_commit(){ asm volatile("cp.async.commit_group;"); }
__device__ __forceinline__ void cpa_wait0(){ asm volatile("cp.async.wait_group 0;"); }

// perm32: word w of a 32-half chunk = j*4+hi*2+s holds halves (s*16+hi*8+2j, +1)
__device__ __forceinline__ int perm_w(int h32){
    int s = (h32 >> 4) & 1, hi = (h32 >> 3) & 1, j = (h32 & 7) >> 1;
    return j*4 + hi*2 + s;
}

// ================= merged fused flash kernel (fp16) =================
__global__ void __launch_bounds__(256, 2)
flash_kernel(){
    extern __shared__ uint32_t smw[];
    const __half *X, *Y, *VT; __half* Mid; int M, Nk, mb;
    if (blockIdx.x < 4){ X=g_u; Y=g_v; VT=g_pT; Mid=g_Pmid; M=NQ; Nk=NK; mb=blockIdx.x; }
    else               { X=g_v; Y=g_u; VT=g_gT; Mid=g_Dmid; M=NK; Nk=NQ; mb=blockIdx.x-4; }
    const int bh = blockIdx.y;
    const int m0 = mb * 128;
    const int tid = threadIdx.x, w = tid >> 5, lane = tid & 31;
    const int g = lane >> 2, tq = lane & 3;
    const int Nk2 = Nk >> 1;
    const uint32_t* Xw = (const uint32_t*)(X + ((size_t)bh*M + m0)*DH);
    const uint32_t* Yw = (const uint32_t*)(Y + (size_t)bh*Nk*DH);
    const uint32_t* Vw = (const uint32_t*)(VT + (size_t)bh*DH*Nk);

    // stage X tile (128 rows x 64 words)
    #pragma unroll
    for (int i = 0; i < 8; i++){
        int u = tid + i*256;
        int r = u >> 4, wq = u & 15;
        *(uint4*)(smw + FL_XS + r*XSTR + wq*4) = *(const uint4*)(Xw + (size_t)r*64 + wq*4);
    }
    __syncthreads();

    const int NT = Nk / 32;
    uint32_t smbase = (uint32_t)__cvta_generic_to_shared(smw);
    {
        #pragma unroll
        for (int i = 0; i < 2; i++){
            int u = tid + i*256;
            int r = u >> 4, wq = u & 15;
            cpa16(smbase + (FL_VB0 + r*80 + wq*4)*4, Yw + (size_t)r*64 + wq*4);
        }
        #pragma unroll
        for (int i = 0; i < 2; i++){
            int u = tid + i*256;
            int r = u >> 2, wq = u & 3;
            cpa16(smbase + (FL_PB0 + r*16 + wq*4)*4, Vw + (size_t)r*Nk2 + wq*4);
        }
        cpa_commit();
    }

    float acc[16][4] = {};
    float rs0 = 0.f, rs1 = 0.f;
    int buf = 0;

    for (int kt = 0; kt < NT; kt++){
        cpa_wait0();
        __syncthreads();

        if (kt + 1 < NT){
            int vb = buf ? FL_VB0 : FL_VB1;
            int pb = buf ? FL_PB0 : FL_PB1;
            #pragma unroll
            for (int i = 0; i < 2; i++){
                int u = tid + i*256;
                int r = u >> 4, wq = u & 15;
                cpa16(smbase + (vb + r*80 + wq*4)*4, Yw + (size_t)((kt+1)*32 + r)*64 + wq*4);
            }
            #pragma unroll
            for (int i = 0; i < 2; i++){
                int u = tid + i*256;
                int r = u >> 2, wq = u & 3;
                cpa16(smbase + (pb + r*16 + wq*4)*4, Vw + (size_t)r*Nk2 + (kt+1)*16 + wq*4);
            }
            cpa_commit();
        }

        const int vb = buf ? FL_VB1 : FL_VB0;
        const int pb = buf ? FL_PB1 : FL_PB0;

        // gemm1: S[16 x 32] per warp
        float cs[4][4] = {};
        #pragma unroll
        for (int kk2 = 0; kk2 < 4; kk2++){
            uint4 xa = *(const uint4*)(smw + FL_XS + (w*16 + g)*XSTR + kk2*16 + tq*4);
            uint4 xb = *(const uint4*)(smw + FL_XS + (w*16 + g + 8)*XSTR + kk2*16 + tq*4);
            #pragma unroll
            for (int ni = 0; ni < 4; ni++){
                uint4 r = *(const uint4*)(smw + vb + (ni*8 + g)*80 + kk2*16 + tq*4);
                mma16h(cs[ni], xa.x, xb.x, xa.z, xb.z, r.x, r.z);
                mma16h(cs[ni], xa.y, xb.y, xa.w, xb.w, r.y, r.w);
            }
        }

        // exp + rowsum + pack to A-fragments
        uint32_t eh[4][2];
        #pragma unroll
        for (int ni = 0; ni < 4; ni++){
            float e0 = exp2f(cs[ni][0]*SC2), e1 = exp2f(cs[ni][1]*SC2);
            float e2 = exp2f(cs[ni][2]*SC2), e3 = exp2f(cs[ni][3]*SC2);
            rs0 += e0 + e1; rs1 += e2 + e3;
            eh[ni][0] = packh2(e0, e1);
            eh[ni][1] = packh2(e2, e3);
        }

        // gemm2: acc[16 x 128] per warp
        #pragma unroll
        for (int n2 = 0; n2 < 16; n2++){
            uint4 r = *(const uint4*)(smw + pb + (n2*8 + g)*16 + tq*4);
            mma16h(acc[n2], eh[0][0], eh[0][1], eh[1][0], eh[1][1], r.x, r.z);
            mma16h(acc[n2], eh[2][0], eh[2][1], eh[3][0], eh[3][1], r.y, r.w);
        }
        buf ^= 1;
    }

    // normalize + store in perm32 layout (for cp.async consumption by outproj)
    rs0 += __shfl_xor_sync(0xffffffffu, rs0, 1);
    rs0 += __shfl_xor_sync(0xffffffffu, rs0, 2);
    rs1 += __shfl_xor_sync(0xffffffffu, rs1, 1);
    rs1 += __shfl_xor_sync(0xffffffffu, rs1, 2);
    float i0 = 1.0f / rs0, i1 = 1.0f / rs1;
    int b = bh >> 3, h = bh & 7;
    int mg = m0 + w*16 + g;
    uint32_t* o0 = (uint32_t*)Mid + (((size_t)(b*M + mg    )*HEADS + h) << 6);
    uint32_t* o8 = (uint32_t*)Mid + (((size_t)(b*M + mg + 8)*HEADS + h) << 6);
    #pragma unroll
    for (int n2 = 0; n2 < 16; n2++){
        int col = n2*8 + 2*tq;
        int wrd = ((col >> 5) << 4) + perm_w(col & 31);
        o0[wrd] = packh2(acc[n2][0]*i0, acc[n2][1]*i0);
        o8[wrd] = packh2(acc[n2][2]*i1, acc[n2][3]*i1);
    }
}

// ================= fused input projection (fp16 mma) =================
// C[128x64] = X[128x128] @ W[64x128]^T + bias; branch 0 -> plain perm32 Y1,
// branch 1 -> transposed perm32 Y2.
__global__ void __launch_bounds__(256)
proj_fused_kernel(const float* __restrict__ X,
                  const float* __restrict__ W1, const float* __restrict__ b1, __half* __restrict__ Y1,
                  const float* __restrict__ W2, const float* __restrict__ b2, __half* __restrict__ Y2,
                  int Nrows, int nshift)
{
    extern __shared__ uint32_t smw[];
    const int m0 = blockIdx.x*128;
    const int trans = blockIdx.y >> 4;
    const int n0 = (blockIdx.y & 15) * 64;
    const float* W    = trans ? W2 : W1;
    const float* bias = trans ? b2 : b1;
    __half* Yout      = trans ? Y2 : Y1;
    const int tid = threadIdx.x, w = tid >> 5, lane = tid & 31;
    const int g = lane >> 2, tq = lane & 3;

    // stage X (rows w*16+g+{0,8}) and W (rows w*8+g) fp32 -> fp16 perm32
    {
        const float* Xb = X + (size_t)m0*DH;
        #pragma unroll
        for (int mi = 0; mi < 2; mi++){
            int r = w*16 + g + mi*8;
            const float* src = Xb + (size_t)r*DH;
            #pragma unroll
            for (int cH = 0; cH < 4; cH++){
                float2 f0 = *(const float2*)(src + cH*32 + 2*tq);
                float2 f1 = *(const float2*)(src + cH*32 + 2*tq + 16);
                float2 f2 = *(const float2*)(src + cH*32 + 2*tq + 8);
                float2 f3 = *(const float2*)(src + cH*32 + 2*tq + 24);
                *(uint4*)(smw + r*80 + cH*16 + tq*4) =
                    make_uint4(packh2(f0.x,f0.y), packh2(f1.x,f1.y),
                               packh2(f2.x,f2.y), packh2(f3.x,f3.y));
            }
        }
        int r = w*8 + g;
        const float* src = W + (size_t)(n0 + r)*DH;
        #pragma unroll
        for (int cH = 0; cH < 4; cH++){
            float2 f0 = *(const float2*)(src + cH*32 + 2*tq);
            float2 f1 = *(const float2*)(src + cH*32 + 2*tq + 16);
            float2 f2 = *(const float2*)(src + cH*32 + 2*tq + 8);
            float2 f3 = *(const float2*)(src + cH*32 + 2*tq + 24);
            *(uint4*)(smw + 128*80 + r*80 + cH*16 + tq*4) =
                make_uint4(packh2(f0.x,f0.y), packh2(f1.x,f1.y),
                           packh2(f2.x,f2.y), packh2(f3.x,f3.y));
        }
    }
    __syncthreads();

    const int wm = w >> 1, wn = w & 1;
    float c[2][4][4] = {};
    const uint32_t* Xs = smw;
    const uint32_t* Ws = smw + 128*80;
    #pragma unroll
    for (int kk = 0; kk < 4; kk++){
        uint4 xa[2], xb[2];
        #pragma unroll
        for (int mi = 0; mi < 2; mi++){
            xa[mi] = *(const uint4*)(Xs + (wm*32+mi*16+g)*80 + kk*16 + tq*4);
            xb[mi] = *(const uint4*)(Xs + (wm*32+mi*16+g+8)*80 + kk*16 + tq*4);
        }
        #pragma unroll
        for (int ni = 0; ni < 4; ni++){
            uint4 bb = *(const uint4*)(Ws + (wn*32+ni*8+g)*80 + kk*16 + tq*4);
            #pragma unroll
            for (int mi = 0; mi < 2; mi++){
                mma16h(c[mi][ni], xa[mi].x, xb[mi].x, xa[mi].z, xb[mi].z, bb.x, bb.z);
                mma16h(c[mi][ni], xa[mi].y, xb[mi].y, xa[mi].w, xb[mi].w, bb.y, bb.w);
            }
        }
    }
    __syncthreads();

    if (!trans){
        uint32_t* Yw = (uint32_t*)Yout;
        #pragma unroll
        for (int mi=0;mi<2;mi++)
        #pragma unroll
        for (int hh=0;hh<2;hh++)
        #pragma unroll
        for (int ni=0;ni<4;ni++){
            int row = m0 + wm*32 + mi*16 + g + hh*8;
            int cg  = n0 + wn*32 + ni*8 + tq*2;
            int b = row >> nshift, n = row - (b << nshift);
            int h = cg >> 7, d = cg & 127;
            int wrd = ((d >> 5) << 4) + perm_w(d & 31);
            Yw[(size_t)((b*HEADS + h)*Nrows + n)*64 + wrd] =
                packh2(c[mi][ni][hh*2] + bias[cg], c[mi][ni][hh*2+1] + bias[cg+1]);
        }
    } else {
        float* tr = (float*)smw;
        #pragma unroll
        for (int mi=0;mi<2;mi++)
        #pragma unroll
        for (int hh=0;hh<2;hh++)
        #pragma unroll
        for (int ni=0;ni<4;ni++)
        #pragma unroll
        for (int cc=0;cc<2;cc++){
            int rl = wm*32 + mi*16 + g + hh*8;
            int cl = wn*32 + ni*8 + tq*2 + cc;
            tr[cl*TRP + rl] = c[mi][ni][hh*2+cc] + bias[n0+cl];
        }
        __syncthreads();
        int b = m0 >> nshift, nloc0 = m0 - (b << nshift);
        int h = n0 >> 7, d0 = n0 & 127;
        int cl = tid >> 2, cch = tid & 3;
        const float* src = tr + cl*TRP + cch*32;
        uint32_t wds[16];
        #pragma unroll
        for (int wd = 0; wd < 16; wd++){
            int j = wd >> 2, hi = (wd >> 1) & 1, s = wd & 1;
            int h0 = s*16 + hi*8 + 2*j;
            wds[wd] = packh2(src[h0], src[h0+1]);
        }
        uint32_t* Yw = (uint32_t*)Yout;
        uint32_t* dst = Yw + ((size_t)(b*HEADS + h)*DH + d0 + cl)*(size_t)(Nrows>>1) + (nloc0>>1) + cch*16;
        #pragma unroll
        for (int q = 0; q < 4; q++)
            ((uint4*)dst)[q] = make_uint4(wds[q*4], wds[q*4+1], wds[q*4+2], wds[q*4+3]);
    }
}

// ================= Wo fp32 -> fp16 perm32 convert =================
__global__ void convw_kernel(const float* __restrict__ Wo1, const float* __restrict__ Wo2){
    int idx = blockIdx.x*256 + threadIdx.x;   // 0..131071
    int wsel = idx >> 16;
    int rem  = idx & 65535;
    int r = rem >> 9, w9 = rem & 511;
    int chunk = w9 >> 4, wd = w9 & 15;
    int j = wd >> 2, hi = (wd >> 1) & 1, s = wd & 1;
    int k0 = chunk*32 + s*16 + hi*8 + 2*j;
    const float* src = (wsel ? Wo2 : Wo1) + (size_t)r*1024 + k0;
    uint32_t* dst = (uint32_t*)(wsel ? g_Wo2h : g_Wo1h);
    dst[r*512 + w9] = packh2(src[0], src[1]);
}

// ================= output projection (fp16 cp.async GEMM) =================
__global__ void __launch_bounds__(256)
outproj_kernel(const __half* __restrict__ Xh, const __half* __restrict__ Wh,
               const float* __restrict__ bias, float* __restrict__ out){
    __shared__ uint32_t As[2][128*16];
    __shared__ uint32_t Bs[2][64*16];
    const int m0 = blockIdx.x*128, n0 = blockIdx.y*64;
    const int tid = threadIdx.x, w = tid >> 5, lane = tid & 31;
    const int g = lane >> 2, tq = lane & 3;
    const int wm = w >> 1, wn = w & 1;
    const uint32_t* Xw = (const uint32_t*)Xh + (size_t)m0*512;
    const uint32_t* Ww = (const uint32_t*)Wh + (size_t)n0*512;
    uint32_t sa = (uint32_t)__cvta_generic_to_shared(&As[0][0]);
    uint32_t sb = (uint32_t)__cvta_generic_to_shared(&Bs[0][0]);

    float c[2][4][4] = {};
    // issue tile 0
    {
        #pragma unroll
        for (int i = 0; i < 2; i++){
            int u = tid + i*256; int r = u >> 2, q = u & 3;
            cpa16(sa + (r*16 + q*4)*4, Xw + (size_t)r*512 + q*4);
        }
        { int r = tid >> 2, q = tid & 3;
          cpa16(sb + (r*16 + q*4)*4, Ww + (size_t)r*512 + q*4); }
        cpa_commit();
    }

    int buf = 0;
    for (int kt = 0; kt < 32; kt++){
        cpa_wait0();
        __syncthreads();
        if (kt + 1 < 32){
            int nb = buf ^ 1;
            #pragma unroll
            for (int i = 0; i < 2; i++){
                int u = tid + i*256; int r = u >> 2, q = u & 3;
                cpa16(sa + (nb*2048 + r*16 + q*4)*4, Xw + (size_t)r*512 + (kt+1)*16 + q*4);
            }
            { int r = tid >> 2, q = tid & 3;
              cpa16(sb + (nb*1024 + r*16 + q*4)*4, Ww + (size_t)r*512 + (kt+1)*16 + q*4); }
            cpa_commit();
        }
        const uint32_t* A = &As[buf][0];
        const uint32_t* B = &Bs[buf][0];
        uint4 xa[2], xb[2];
        #pragma unroll
        for (int mi = 0; mi < 2; mi++){
            xa[mi] = *(const uint4*)(A + (wm*32+mi*16+g)*16 + tq*4);
            xb[mi] = *(const uint4*)(A + (wm*32+mi*16+g+8)*16 + tq*4);
        }
        #pragma unroll
        for (int ni = 0; ni < 4; ni++){
            uint4 bb = *(const uint4*)(B + (wn*32+ni*8+g)*16 + tq*4);
            #pragma unroll
            for (int mi = 0; mi < 2; mi++){
                mma16h(c[mi][ni], xa[mi].x, xb[mi].x, xa[mi].z, xb[mi].z, bb.x, bb.z);
                mma16h(c[mi][ni], xa[mi].y, xb[mi].y, xa[mi].w, xb[mi].w, bb.y, bb.w);
            }
        }
        buf ^= 1;
    }

    #pragma unroll
    for (int mi=0;mi<2;mi++)
    #pragma unroll
    for (int hh=0;hh<2;hh++)
    #pragma unroll
    for (int ni=0;ni<4;ni++)
    #pragma unroll
    for (int cc=0;cc<2;cc++){
        int row = m0 + wm*32 + mi*16 + g + hh*8;
        int col = n0 + wn*32 + ni*8 + tq*2 + cc;
        out[((size_t)row << 7) + col] = c[mi][ni][hh*2+cc] + bias[col];
    }
}

// ---------------- launch ----------------
extern "C" void kernel_launch(void* const* d_in, const int* in_sizes, int n_in,
                              void* d_out, int out_size){
    const float* queries = (const float*)d_in[0];
    const float* keys    = (const float*)d_in[1];
    const float* Wq  = (const float*)d_in[2];
    const float* bq  = (const float*)d_in[3];
    const float* Wk  = (const float*)d_in[4];
    const float* bk  = (const float*)d_in[5];
    const float* Wp  = (const float*)d_in[6];
    const float* bp  = (const float*)d_in[7];
    const float* Wg  = (const float*)d_in[8];
    const float* bg  = (const float*)d_in[9];
    const float* Wo1 = (const float*)d_in[10];
    const float* bo1 = (const float*)d_in[11];
    const float* Wo2 = (const float*)d_in[12];
    const float* bo2 = (const float*)d_in[13];
    float* out = (float*)d_out;

    __half *pu, *pv, *ppT, *pgT, *pPmid, *pDmid, *pW1h, *pW2h;
    cudaGetSymbolAddress((void**)&pu,    g_u);
    cudaGetSymbolAddress((void**)&pv,    g_v);
    cudaGetSymbolAddress((void**)&ppT,   g_pT);
    cudaGetSymbolAddress((void**)&pgT,   g_gT);
    cudaGetSymbolAddress((void**)&pPmid, g_Pmid);
    cudaGetSymbolAddress((void**)&pDmid, g_Dmid);
    cudaGetSymbolAddress((void**)&pW1h,  g_Wo1h);
    cudaGetSymbolAddress((void**)&pW2h,  g_Wo2h);

    cudaFuncSetAttribute(proj_fused_kernel, cudaFuncAttributeMaxDynamicSharedMemorySize, PRJ_WORDS*4);
    cudaFuncSetAttribute(flash_kernel,      cudaFuncAttributeMaxDynamicSharedMemorySize, FL_BYTES);

    // Wo -> fp16 perm32 (independent; overlaps nothing it shouldn't)
    convw_kernel<<<512, 256>>>(Wo1, Wo2);

    // projections: queries -> (u plain | gT trans), keys -> (v plain | pT trans)
    proj_fused_kernel<<<dim3(64, 32), 256, PRJ_WORDS*4>>>(
        queries, Wq, bq, pu, Wg, bg, pgT, NQ, 9);
    proj_fused_kernel<<<dim3(128, 32), 256, PRJ_WORDS*4>>>(
        keys, Wk, bk, pv, Wp, bp, ppT, NK, 10);

    // both attention branches, one launch
    flash_kernel<<<dim3(12, BH), 256, FL_BYTES>>>();

    // output projections
    outproj_kernel<<<dim3(BATCH*NQ/128, 2), 256>>>(pPmid, pW1h, bo1, out);
    outproj_kernel<<<dim3(BATCH*NK/128, 2), 256>>>(pDmid, pW2h, bo2, out + (size_t)BATCH*NQ*DH);
}

// round 8
// speedup vs baseline: 2.3605x; 1.0333x over previous
#include <cuda_runtime.h>
#include <cuda_fp16.h>
#include <cstdint>
#include <cstddef>

// ---------------- problem constants ----------------
#define BATCH 16
#define NQ    512
#define NK    1024
#define DH    128
#define HEADS 8
#define BH    (BATCH*HEADS)        // 128
#define SC2   0.12751741254364243f // (1/sqrt(128)) * log2(e)

// ---------------- proj smem ----------------
#define PRJ_WORDS (128*80 + 64*80) // 61440 B
#define TRP 136

// ---------------- device scratch (fp16, perm32 along K dim) ----------------
__device__ __half g_u  [(size_t)BH*NQ*DH];
__device__ __half g_v  [(size_t)BH*NK*DH];
__device__ __half g_pT [(size_t)BH*DH*NK];
__device__ __half g_gT [(size_t)BH*DH*NQ];
__device__ __half g_Pmid[(size_t)BATCH*NQ*HEADS*DH]; // perm32 rows of 1024
__device__ __half g_Dmid[(size_t)BATCH*NK*HEADS*DH];
__device__ __half g_Wo1h[128*1024];                  // perm32
__device__ __half g_Wo2h[128*1024];

// ---------------- helpers ----------------
__device__ __forceinline__ uint32_t packh2(float a, float b){
    __half2 h = __floats2half2_rn(a, b);
    return *reinterpret_cast<uint32_t*>(&h);
}
__device__ __forceinline__ void mma16h(float (&c)[4], uint32_t a0, uint32_t a1, uint32_t a2, uint32_t a3,
                                       uint32_t b0, uint32_t b1){
    asm volatile("mma.sync.aligned.m16n8k16.row.col.f32.f16.f16.f32 "
        "{%0,%1,%2,%3}, {%4,%5,%6,%7}, {%8,%9}, {%0,%1,%2,%3};"
        : "+f"(c[0]),"+f"(c[1]),"+f"(c[2]),"+f"(c[3])
        : "r"(a0),"r"(a1),"r"(a2),"r"(a3), "r"(b0),"r"(b1));
}
__device__ __forceinline__ void cpa16(uint32_t dst_shared, const void* src){
    asm volatile("cp.async.cg.shared.global [%0], [%1], 16;" :: "r"(dst_shared), "l"(src));
}
__device__ __forceinline__ void cpa_commit(){ asm volatile("cp.async.commit_group;"); }
__device__ __forceinline__ void cpa_wait0(){ asm volatile("cp.async.wait_group 0;"); }

// perm32: word w of a 32-half chunk = j*4+hi*2+s holds halves (s*16+hi*8+2j, +1)
__device__ __forceinline__ int perm_w(int h32){
    int s = (h32 >> 4) & 1, hi = (h32 >> 3) & 1, j = (h32 & 7) >> 1;
    return j*4 + hi*2 + s;
}

// ================= merged fused flash kernel (fp16 mma.sync) =================
// X-fragments register-resident (loaded once from gmem); smem only holds the
// double-buffered Y (keys) and P (values-T) tiles.
__global__ void __launch_bounds__(256, 2)
flash_kernel(){
    __shared__ uint32_t sY[2][32*80];
    __shared__ uint32_t sP[2][128*16];
    const __half *X, *Y, *VT; __half* Mid; int M, Nk, mb;
    if (blockIdx.x < 4){ X=g_u; Y=g_v; VT=g_pT; Mid=g_Pmid; M=NQ; Nk=NK; mb=blockIdx.x; }
    else               { X=g_v; Y=g_u; VT=g_gT; Mid=g_Dmid; M=NK; Nk=NQ; mb=blockIdx.x-4; }
    const int bh = blockIdx.y;
    const int m0 = mb * 128;
    const int tid = threadIdx.x, w = tid >> 5, lane = tid & 31;
    const int g = lane >> 2, tq = lane & 3;
    const int Nk2 = Nk >> 1;
    const int NT = Nk / 32;
    const uint32_t* Xw = (const uint32_t*)(X + ((size_t)bh*M + m0)*DH);
    const uint32_t* Yw = (const uint32_t*)(Y + (size_t)bh*Nk*DH);
    const uint32_t* Vw = (const uint32_t*)(VT + (size_t)bh*DH*Nk);

    uint32_t syb[2], spb[2];
    syb[0] = (uint32_t)__cvta_generic_to_shared(&sY[0][0]);
    syb[1] = (uint32_t)__cvta_generic_to_shared(&sY[1][0]);
    spb[0] = (uint32_t)__cvta_generic_to_shared(&sP[0][0]);
    spb[1] = (uint32_t)__cvta_generic_to_shared(&sP[1][0]);

    // ---- X A-fragments: registers, loaded once (perm32 gmem rows) ----
    uint4 xa[4], xb[4];
    {
        const uint32_t* Xr = Xw + (size_t)(w*16 + g)*64 + tq*4;
        #pragma unroll
        for (int kk2 = 0; kk2 < 4; kk2++){
            xa[kk2] = *(const uint4*)(Xr + kk2*16);
            xb[kk2] = *(const uint4*)(Xr + 8*64 + kk2*16);
        }
    }

    // ---- issue tile 0 ----
    {
        #pragma unroll
        for (int i = 0; i < 2; i++){
            int u = tid + i*256;
            int r = u >> 4, wq = u & 15;
            cpa16(syb[0] + (r*80 + wq*4)*4, Yw + (size_t)r*64 + wq*4);
        }
        #pragma unroll
        for (int i = 0; i < 2; i++){
            int u = tid + i*256;
            int r = u >> 2, q = u & 3;
            cpa16(spb[0] + (r*16 + q*4)*4, Vw + (size_t)r*Nk2 + q*4);
        }
        cpa_commit();
    }

    float acc[16][4] = {};
    float rs0 = 0.f, rs1 = 0.f;
    int buf = 0;

    for (int kt = 0; kt < NT; kt++){
        cpa_wait0();
        __syncthreads();

        // prefetch next tile into other buffer
        if (kt + 1 < NT){
            int nb = buf ^ 1;
            #pragma unroll
            for (int i = 0; i < 2; i++){
                int u = tid + i*256;
                int r = u >> 4, wq = u & 15;
                cpa16(syb[nb] + (r*80 + wq*4)*4, Yw + (size_t)((kt+1)*32 + r)*64 + wq*4);
            }
            #pragma unroll
            for (int i = 0; i < 2; i++){
                int u = tid + i*256;
                int r = u >> 2, q = u & 3;
                cpa16(spb[nb] + (r*16 + q*4)*4, Vw + (size_t)r*Nk2 + (kt+1)*16 + q*4);
            }
            cpa_commit();
        }

        const uint32_t* Ys = &sY[buf][0];
        const uint32_t* Ps = &sP[buf][0];

        // ---- gemm1 + softmax, per-ni (keeps live regs small) ----
        uint32_t eh[4][2];
        #pragma unroll
        for (int ni = 0; ni < 4; ni++){
            float cs[4] = {0.f, 0.f, 0.f, 0.f};
            #pragma unroll
            for (int kk2 = 0; kk2 < 4; kk2++){
                uint4 r = *(const uint4*)(Ys + (ni*8 + g)*80 + kk2*16 + tq*4);
                mma16h(cs, xa[kk2].x, xb[kk2].x, xa[kk2].z, xb[kk2].z, r.x, r.z);
                mma16h(cs, xa[kk2].y, xb[kk2].y, xa[kk2].w, xb[kk2].w, r.y, r.w);
            }
            float e0 = exp2f(cs[0]*SC2), e1 = exp2f(cs[1]*SC2);
            float e2 = exp2f(cs[2]*SC2), e3 = exp2f(cs[3]*SC2);
            rs0 += e0 + e1; rs1 += e2 + e3;
            eh[ni][0] = packh2(e0, e1);
            eh[ni][1] = packh2(e2, e3);
        }

        // ---- gemm2: acc[16 x 128] per warp ----
        #pragma unroll
        for (int n2 = 0; n2 < 16; n2++){
            uint4 r = *(const uint4*)(Ps + (n2*8 + g)*16 + tq*4);
            mma16h(acc[n2], eh[0][0], eh[0][1], eh[1][0], eh[1][1], r.x, r.z);
            mma16h(acc[n2], eh[2][0], eh[2][1], eh[3][0], eh[3][1], r.y, r.w);
        }
        buf ^= 1;
    }

    // ---- normalize + store perm32 ----
    rs0 += __shfl_xor_sync(0xffffffffu, rs0, 1);
    rs0 += __shfl_xor_sync(0xffffffffu, rs0, 2);
    rs1 += __shfl_xor_sync(0xffffffffu, rs1, 1);
    rs1 += __shfl_xor_sync(0xffffffffu, rs1, 2);
    float i0 = 1.0f / rs0, i1 = 1.0f / rs1;
    int b = bh >> 3, h = bh & 7;
    int mg = m0 + w*16 + g;
    uint32_t* o0 = (uint32_t*)Mid + (((size_t)(b*M + mg    )*HEADS + h) << 6);
    uint32_t* o8 = (uint32_t*)Mid + (((size_t)(b*M + mg + 8)*HEADS + h) << 6);
    #pragma unroll
    for (int n2 = 0; n2 < 16; n2++){
        int col = n2*8 + 2*tq;
        int wrd = ((col >> 5) << 4) + perm_w(col & 31);
        o0[wrd] = packh2(acc[n2][0]*i0, acc[n2][1]*i0);
        o8[wrd] = packh2(acc[n2][2]*i1, acc[n2][3]*i1);
    }
}

// ================= merged input projections (fp16 mma) =================
// grid.x: [0,64) queries-tiles, [64,192) keys-tiles. grid.y: 32
//   y<16 -> plain perm32 output (Wq->u / Wk->v); y>=16 -> transposed (Wg->gT / Wp->pT)
__global__ void __launch_bounds__(256)
proj_fused_kernel(const float* __restrict__ queries, const float* __restrict__ keys,
                  const float* __restrict__ Wq, const float* __restrict__ bq,
                  const float* __restrict__ Wk, const float* __restrict__ bk,
                  const float* __restrict__ Wp, const float* __restrict__ bp,
                  const float* __restrict__ Wg, const float* __restrict__ bg)
{
    extern __shared__ uint32_t smw[];
    const int bx = blockIdx.x;
    const bool isK = (bx >= 64);
    const int m0 = (isK ? bx - 64 : bx) * 128;
    const int trans = blockIdx.y >> 4;
    const int n0 = (blockIdx.y & 15) * 64;
    const float* X    = isK ? keys : queries;
    const int Nrows   = isK ? NK : NQ;
    const int nshift  = isK ? 10 : 9;
    const float* W    = trans ? (isK ? Wp : Wg) : (isK ? Wk : Wq);
    const float* bias = trans ? (isK ? bp : bg) : (isK ? bk : bq);
    __half* Yout      = trans ? (isK ? g_pT : g_gT) : (isK ? g_v : g_u);
    const int tid = threadIdx.x, w = tid >> 5, lane = tid & 31;
    const int g = lane >> 2, tq = lane & 3;

    // stage X and W fp32 -> fp16 perm32
    {
        const float* Xb = X + (size_t)m0*DH;
        #pragma unroll
        for (int mi = 0; mi < 2; mi++){
            int r = w*16 + g + mi*8;
            const float* src = Xb + (size_t)r*DH;
            #pragma unroll
            for (int cH = 0; cH < 4; cH++){
                float2 f0 = *(const float2*)(src + cH*32 + 2*tq);
                float2 f1 = *(const float2*)(src + cH*32 + 2*tq + 16);
                float2 f2 = *(const float2*)(src + cH*32 + 2*tq + 8);
                float2 f3 = *(const float2*)(src + cH*32 + 2*tq + 24);
                *(uint4*)(smw + r*80 + cH*16 + tq*4) =
                    make_uint4(packh2(f0.x,f0.y), packh2(f1.x,f1.y),
                               packh2(f2.x,f2.y), packh2(f3.x,f3.y));
            }
        }
        int r = w*8 + g;
        const float* src = W + (size_t)(n0 + r)*DH;
        #pragma unroll
        for (int cH = 0; cH < 4; cH++){
            float2 f0 = *(const float2*)(src + cH*32 + 2*tq);
            float2 f1 = *(const float2*)(src + cH*32 + 2*tq + 16);
            float2 f2 = *(const float2*)(src + cH*32 + 2*tq + 8);
            float2 f3 = *(const float2*)(src + cH*32 + 2*tq + 24);
            *(uint4*)(smw + 128*80 + r*80 + cH*16 + tq*4) =
                make_uint4(packh2(f0.x,f0.y), packh2(f1.x,f1.y),
                           packh2(f2.x,f2.y), packh2(f3.x,f3.y));
        }
    }
    __syncthreads();

    const int wm = w >> 1, wn = w & 1;
    float c[2][4][4] = {};
    const uint32_t* Xs = smw;
    const uint32_t* Ws = smw + 128*80;
    #pragma unroll
    for (int kk = 0; kk < 4; kk++){
        uint4 xa[2], xb[2];
        #pragma unroll
        for (int mi = 0; mi < 2; mi++){
            xa[mi] = *(const uint4*)(Xs + (wm*32+mi*16+g)*80 + kk*16 + tq*4);
            xb[mi] = *(const uint4*)(Xs + (wm*32+mi*16+g+8)*80 + kk*16 + tq*4);
        }
        #pragma unroll
        for (int ni = 0; ni < 4; ni++){
            uint4 bb = *(const uint4*)(Ws + (wn*32+ni*8+g)*80 + kk*16 + tq*4);
            #pragma unroll
            for (int mi = 0; mi < 2; mi++){
                mma16h(c[mi][ni], xa[mi].x, xb[mi].x, xa[mi].z, xb[mi].z, bb.x, bb.z);
                mma16h(c[mi][ni], xa[mi].y, xb[mi].y, xa[mi].w, xb[mi].w, bb.y, bb.w);
            }
        }
    }
    __syncthreads();

    if (!trans){
        uint32_t* Yw = (uint32_t*)Yout;
        #pragma unroll
        for (int mi=0;mi<2;mi++)
        #pragma unroll
        for (int hh=0;hh<2;hh++)
        #pragma unroll
        for (int ni=0;ni<4;ni++){
            int row = m0 + wm*32 + mi*16 + g + hh*8;
            int cg  = n0 + wn*32 + ni*8 + tq*2;
            int b = row >> nshift, n = row - (b << nshift);
            int h = cg >> 7, d = cg & 127;
            int wrd = ((d >> 5) << 4) + perm_w(d & 31);
            Yw[(size_t)((b*HEADS + h)*Nrows + n)*64 + wrd] =
                packh2(c[mi][ni][hh*2] + bias[cg], c[mi][ni][hh*2+1] + bias[cg+1]);
        }
    } else {
        float* tr = (float*)smw;
        #pragma unroll
        for (int mi=0;mi<2;mi++)
        #pragma unroll
        for (int hh=0;hh<2;hh++)
        #pragma unroll
        for (int ni=0;ni<4;ni++)
        #pragma unroll
        for (int cc=0;cc<2;cc++){
            int rl = wm*32 + mi*16 + g + hh*8;
            int cl = wn*32 + ni*8 + tq*2 + cc;
            tr[cl*TRP + rl] = c[mi][ni][hh*2+cc] + bias[n0+cl];
        }
        __syncthreads();
        int b = m0 >> nshift, nloc0 = m0 - (b << nshift);
        int h = n0 >> 7, d0 = n0 & 127;
        int cl = tid >> 2, cch = tid & 3;
        const float* src = tr + cl*TRP + cch*32;
        uint32_t wds[16];
        #pragma unroll
        for (int wd = 0; wd < 16; wd++){
            int j = wd >> 2, hi = (wd >> 1) & 1, s = wd & 1;
            int h0 = s*16 + hi*8 + 2*j;
            wds[wd] = packh2(src[h0], src[h0+1]);
        }
        uint32_t* Yw = (uint32_t*)Yout;
        uint32_t* dst = Yw + ((size_t)(b*HEADS + h)*DH + d0 + cl)*(size_t)(Nrows>>1) + (nloc0>>1) + cch*16;
        #pragma unroll
        for (int q = 0; q < 4; q++)
            ((uint4*)dst)[q] = make_uint4(wds[q*4], wds[q*4+1], wds[q*4+2], wds[q*4+3]);
    }
}

// ================= Wo fp32 -> fp16 perm32 convert =================
__global__ void convw_kernel(const float* __restrict__ Wo1, const float* __restrict__ Wo2){
    int idx = blockIdx.x*256 + threadIdx.x;
    int wsel = idx >> 16;
    int rem  = idx & 65535;
    int r = rem >> 9, w9 = rem & 511;
    int chunk = w9 >> 4, wd = w9 & 15;
    int j = wd >> 2, hi = (wd >> 1) & 1, s = wd & 1;
    int k0 = chunk*32 + s*16 + hi*8 + 2*j;
    const float* src = (wsel ? Wo2 : Wo1) + (size_t)r*1024 + k0;
    uint32_t* dst = (uint32_t*)(wsel ? g_Wo2h : g_Wo1h);
    dst[r*512 + w9] = packh2(src[0], src[1]);
}

// ================= merged output projection (fp16 cp.async GEMM) =================
// grid.x: [0,64) P-branch tiles, [64,192) D-branch tiles. grid.y: 2 (n0)
__global__ void __launch_bounds__(256)
outproj_kernel(const float* __restrict__ bo1, const float* __restrict__ bo2,
               float* __restrict__ out){
    __shared__ uint32_t As[2][128*16];
    __shared__ uint32_t Bs[2][64*16];
    const int bx = blockIdx.x;
    const bool isD = (bx >= 64);
    const int m0 = (isD ? bx - 64 : bx) * 128;
    const int n0 = blockIdx.y * 64;
    const __half* Xh = isD ? g_Dmid : g_Pmid;
    const __half* Wh = isD ? g_Wo2h : g_Wo1h;
    const float* bias = isD ? bo2 : bo1;
    float* outp = out + (isD ? (size_t)BATCH*NQ*DH : 0);
    const int tid = threadIdx.x, w = tid >> 5, lane = tid & 31;
    const int g = lane >> 2, tq = lane & 3;
    const int wm = w >> 1, wn = w & 1;
    const uint32_t* Xw = (const uint32_t*)Xh + (size_t)m0*512;
    const uint32_t* Ww = (const uint32_t*)Wh + (size_t)n0*512;
    uint32_t sa = (uint32_t)__cvta_generic_to_shared(&As[0][0]);
    uint32_t sb = (uint32_t)__cvta_generic_to_shared(&Bs[0][0]);

    float c[2][4][4] = {};
    {
        #pragma unroll
        for (int i = 0; i < 2; i++){
            int u = tid + i*256; int r = u >> 2, q = u & 3;
            cpa16(sa + (r*16 + q*4)*4, Xw + (size_t)r*512 + q*4);
        }
        { int r = tid >> 2, q = tid & 3;
          cpa16(sb + (r*16 + q*4)*4, Ww + (size_t)r*512 + q*4); }
        cpa_commit();
    }

    int buf = 0;
    for (int kt = 0; kt < 32; kt++){
        cpa_wait0();
        __syncthreads();
        if (kt + 1 < 32){
            int nb = buf ^ 1;
            #pragma unroll
            for (int i = 0; i < 2; i++){
                int u = tid + i*256; int r = u >> 2, q = u & 3;
                cpa16(sa + (nb*2048 + r*16 + q*4)*4, Xw + (size_t)r*512 + (kt+1)*16 + q*4);
            }
            { int r = tid >> 2, q = tid & 3;
              cpa16(sb + (nb*1024 + r*16 + q*4)*4, Ww + (size_t)r*512 + (kt+1)*16 + q*4); }
            cpa_commit();
        }
        const uint32_t* A = &As[buf][0];
        const uint32_t* B = &Bs[buf][0];
        uint4 xa[2], xb[2];
        #pragma unroll
        for (int mi = 0; mi < 2; mi++){
            xa[mi] = *(const uint4*)(A + (wm*32+mi*16+g)*16 + tq*4);
            xb[mi] = *(const uint4*)(A + (wm*32+mi*16+g+8)*16 + tq*4);
        }
        #pragma unroll
        for (int ni = 0; ni < 4; ni++){
            uint4 bb = *(const uint4*)(B + (wn*32+ni*8+g)*16 + tq*4);
            #pragma unroll
            for (int mi = 0; mi < 2; mi++){
                mma16h(c[mi][ni], xa[mi].x, xb[mi].x, xa[mi].z, xb[mi].z, bb.x, bb.z);
                mma16h(c[mi][ni], xa[mi].y, xb[mi].y, xa[mi].w, xb[mi].w, bb.y, bb.w);
            }
        }
        buf ^= 1;
    }

    #pragma unroll
    for (int mi=0;mi<2;mi++)
    #pragma unroll
    for (int hh=0;hh<2;hh++)
    #pragma unroll
    for (int ni=0;ni<4;ni++)
    #pragma unroll
    for (int cc=0;cc<2;cc++){
        int row = m0 + wm*32 + mi*16 + g + hh*8;
        int col = n0 + wn*32 + ni*8 + tq*2 + cc;
        outp[((size_t)row << 7) + col] = c[mi][ni][hh*2+cc] + bias[col];
    }
}

// ---------------- launch ----------------
extern "C" void kernel_launch(void* const* d_in, const int* in_sizes, int n_in,
                              void* d_out, int out_size){
    const float* queries = (const float*)d_in[0];
    const float* keys    = (const float*)d_in[1];
    const float* Wq  = (const float*)d_in[2];
    const float* bq  = (const float*)d_in[3];
    const float* Wk  = (const float*)d_in[4];
    const float* bk  = (const float*)d_in[5];
    const float* Wp  = (const float*)d_in[6];
    const float* bp  = (const float*)d_in[7];
    const float* Wg  = (const float*)d_in[8];
    const float* bg  = (const float*)d_in[9];
    const float* Wo1 = (const float*)d_in[10];
    const float* bo1 = (const float*)d_in[11];
    const float* Wo2 = (const float*)d_in[12];
    const float* bo2 = (const float*)d_in[13];
    float* out = (float*)d_out;

    cudaFuncSetAttribute(proj_fused_kernel, cudaFuncAttributeMaxDynamicSharedMemorySize, PRJ_WORDS*4);

    convw_kernel<<<512, 256>>>(Wo1, Wo2);

    proj_fused_kernel<<<dim3(192, 32), 256, PRJ_WORDS*4>>>(
        queries, keys, Wq, bq, Wk, bk, Wp, bp, Wg, bg);

    flash_kernel<<<dim3(12, BH), 256>>>();

    outproj_kernel<<<dim3(192, 2), 256>>>(bo1, bo2, out);
}

// round 9
// speedup vs baseline: 2.7449x; 1.1628x over previous
#include <cuda_runtime.h>
#include <cuda_fp16.h>
#include <cstdint>
#include <cstddef>

// ---------------- problem constants ----------------
#define BATCH 16
#define NQ    512
#define NK    1024
#define DH    128
#define HEADS 8
#define BH    (BATCH*HEADS)        // 128
#define SC2   0.12751741254364243f // (1/sqrt(128)) * log2(e)
#define ONESW 0x3C003C00u          // fp16 (1.0, 1.0)

#define TRP 136
#define PRJ_BYTES ((128*80 + 128*80)*4)   // 81920

// ---------------- device scratch (fp16, perm32 along K dim) ----------------
__device__ __half g_qh [8192*DH];               // queries fp16 perm32
__device__ __half g_kh [16384*DH];              // keys fp16 perm32
__device__ __half g_Wqh[1024*DH];
__device__ __half g_Wkh[1024*DH];
__device__ __half g_Wph[1024*DH];
__device__ __half g_Wgh[1024*DH];
__device__ __half g_u  [(size_t)BH*NQ*DH];
__device__ __half g_v  [(size_t)BH*NK*DH];
__device__ __half g_pT [(size_t)BH*DH*NK];
__device__ __half g_gT [(size_t)BH*DH*NQ];
__device__ __half g_Pmid[(size_t)BATCH*NQ*HEADS*DH]; // perm32 rows of 1024
__device__ __half g_Dmid[(size_t)BATCH*NK*HEADS*DH];
__device__ __half g_Wo1h[128*1024];                  // perm32
__device__ __half g_Wo2h[128*1024];

// ---------------- helpers ----------------
__device__ __forceinline__ uint32_t packh2(float a, float b){
    __half2 h = __floats2half2_rn(a, b);
    return *reinterpret_cast<uint32_t*>(&h);
}
__device__ __forceinline__ void mma16h(float (&c)[4], uint32_t a0, uint32_t a1, uint32_t a2, uint32_t a3,
                                       uint32_t b0, uint32_t b1){
    asm volatile("mma.sync.aligned.m16n8k16.row.col.f32.f16.f16.f32 "
        "{%0,%1,%2,%3}, {%4,%5,%6,%7}, {%8,%9}, {%0,%1,%2,%3};"
        : "+f"(c[0]),"+f"(c[1]),"+f"(c[2]),"+f"(c[3])
        : "r"(a0),"r"(a1),"r"(a2),"r"(a3), "r"(b0),"r"(b1));
}
__device__ __forceinline__ void cpa16(uint32_t dst_shared, const void* src){
    asm volatile("cp.async.cg.shared.global [%0], [%1], 16;" :: "r"(dst_shared), "l"(src));
}
__device__ __forceinline__ void cpa_commit(){ asm volatile("cp.async.commit_group;"); }
__device__ __forceinline__ void cpa_wait0(){ asm volatile("cp.async.wait_group 0;"); }

// perm32: word w of a 32-half chunk = j*4+hi*2+s holds halves (s*16+hi*8+2j, +1)
__device__ __forceinline__ int perm_w(int h32){
    int s = (h32 >> 4) & 1, hi = (h32 >> 3) & 1, j = (h32 & 7) >> 1;
    return j*4 + hi*2 + s;
}

// ================= conversion kernel: fp32 -> fp16 perm32 =================
// grid (4096, 8): seg 0=q, 1=k, 2..5=Wq/Wk/Wp/Wg, 6=Wo1, 7=Wo2
__global__ void __launch_bounds__(256)
conv_all_kernel(const float* __restrict__ q, const float* __restrict__ k,
                const float* __restrict__ Wq, const float* __restrict__ Wk,
                const float* __restrict__ Wp, const float* __restrict__ Wg,
                const float* __restrict__ Wo1, const float* __restrict__ Wo2){
    int t = blockIdx.x*256 + threadIdx.x;
    int seg = blockIdx.y;
    const float* src; uint32_t* dst; int nwords;
    switch (seg){
        case 0: src = q;   dst = (uint32_t*)g_qh;  nwords = 8192*64;  break;
        case 1: src = k;   dst = (uint32_t*)g_kh;  nwords = 16384*64; break;
        case 2: src = Wq;  dst = (uint32_t*)g_Wqh; nwords = 1024*64;  break;
        case 3: src = Wk;  dst = (uint32_t*)g_Wkh; nwords = 1024*64;  break;
        case 4: src = Wp;  dst = (uint32_t*)g_Wph; nwords = 1024*64;  break;
        case 5: src = Wg;  dst = (uint32_t*)g_Wgh; nwords = 1024*64;  break;
        case 6: src = Wo1; dst = (uint32_t*)g_Wo1h; nwords = 128*512; break;
        default:src = Wo2; dst = (uint32_t*)g_Wo2h; nwords = 128*512; break;
    }
    if (t >= nwords) return;
    int r, w9, rowfloats;
    if (seg < 6){ r = t >> 6; w9 = t & 63;  rowfloats = 128;  }
    else        { r = t >> 9; w9 = t & 511; rowfloats = 1024; }
    int chunk = w9 >> 4, wd = w9 & 15;
    int j = wd >> 2, hi = (wd >> 1) & 1, s = wd & 1;
    int k0 = chunk*32 + s*16 + hi*8 + 2*j;
    const float* sp = src + (size_t)r*rowfloats + k0;
    dst[t] = packh2(sp[0], sp[1]);
}

// ================= input projections (fp16 cp.async GEMM) =================
// CTA = 128 rows x 128 cols (one head). grid (192, 16):
//   x: [0,64) query row-tiles, [64,192) key row-tiles
//   y: (y&7)=head n-tile, (y>>3)=0 plain (u/v) or 1 transposed (gT/pT)
__global__ void __launch_bounds__(256)
proj_kernel(const float* __restrict__ bq, const float* __restrict__ bk,
            const float* __restrict__ bp, const float* __restrict__ bg){
    extern __shared__ uint32_t smw[];
    const int bx = blockIdx.x;
    const bool isK = (bx >= 64);
    const int m0 = (isK ? bx - 64 : bx) * 128;
    const int trans = blockIdx.y >> 3;
    const int n0 = (blockIdx.y & 7) * 128;
    const __half* Xh  = isK ? g_kh : g_qh;
    const __half* Wh  = trans ? (isK ? g_Wph : g_Wgh) : (isK ? g_Wkh : g_Wqh);
    const float* bias = trans ? (isK ? bp : bg) : (isK ? bk : bq);
    __half* Yout      = trans ? (isK ? g_pT : g_gT) : (isK ? g_v : g_u);
    const int Nrows   = isK ? NK : NQ;
    const int nshift  = isK ? 10 : 9;
    const int tid = threadIdx.x, w = tid >> 5, lane = tid & 31;
    const int g = lane >> 2, tq = lane & 3;
    const int wm = w >> 1, wn = w & 1;

    // stage X (128x128) and W (128x128) fp16 perm32 via cp.async
    uint32_t sx = (uint32_t)__cvta_generic_to_shared(smw);
    uint32_t sw = sx + 10240*4;
    const uint32_t* Xw = (const uint32_t*)Xh + (size_t)m0*64;
    const uint32_t* Ww = (const uint32_t*)Wh + (size_t)n0*64;
    #pragma unroll
    for (int i = 0; i < 8; i++){
        int id = tid + i*256;            // 0..2047
        int r = id >> 4, wq = id & 15;
        cpa16(sx + (r*80 + wq*4)*4, Xw + (size_t)r*64 + wq*4);
        cpa16(sw + (r*80 + wq*4)*4, Ww + (size_t)r*64 + wq*4);
    }
    cpa_commit();
    cpa_wait0();
    __syncthreads();

    float acc[2][8][4] = {};
    const uint32_t* Xs = smw;
    const uint32_t* Ws = smw + 10240;
    #pragma unroll
    for (int kk = 0; kk < 4; kk++){
        uint4 xa[2], xb[2];
        #pragma unroll
        for (int mi = 0; mi < 2; mi++){
            xa[mi] = *(const uint4*)(Xs + (wm*32+mi*16+g)*80 + kk*16 + tq*4);
            xb[mi] = *(const uint4*)(Xs + (wm*32+mi*16+g+8)*80 + kk*16 + tq*4);
        }
        #pragma unroll
        for (int ni = 0; ni < 8; ni++){
            uint4 bb = *(const uint4*)(Ws + (wn*64+ni*8+g)*80 + kk*16 + tq*4);
            #pragma unroll
            for (int mi = 0; mi < 2; mi++){
                mma16h(acc[mi][ni], xa[mi].x, xb[mi].x, xa[mi].z, xb[mi].z, bb.x, bb.z);
                mma16h(acc[mi][ni], xa[mi].y, xb[mi].y, xa[mi].w, xb[mi].w, bb.y, bb.w);
            }
        }
    }
    __syncthreads();   // smem reusable

    const int h = n0 >> 7;
    if (!trans){
        uint32_t* Yw = (uint32_t*)Yout;
        #pragma unroll
        for (int mi = 0; mi < 2; mi++)
        #pragma unroll
        for (int hh = 0; hh < 2; hh++)
        #pragma unroll
        for (int ni = 0; ni < 8; ni++){
            int row = m0 + wm*32 + mi*16 + g + hh*8;
            int d = wn*64 + ni*8 + tq*2;
            int b = row >> nshift, n = row - (b << nshift);
            int wrd = ((d >> 5) << 4) + perm_w(d & 31);
            Yw[(size_t)((b*HEADS + h)*Nrows + n)*64 + wrd] =
                packh2(acc[mi][ni][hh*2] + bias[n0+d], acc[mi][ni][hh*2+1] + bias[n0+d+1]);
        }
    } else {
        float* tr = (float*)smw;   // 128 x TRP = 17408 floats <= 20480
        #pragma unroll
        for (int mi = 0; mi < 2; mi++)
        #pragma unroll
        for (int hh = 0; hh < 2; hh++)
        #pragma unroll
        for (int ni = 0; ni < 8; ni++)
        #pragma unroll
        for (int cc = 0; cc < 2; cc++){
            int rl = wm*32 + mi*16 + g + hh*8;
            int cl = wn*64 + ni*8 + tq*2 + cc;
            tr[cl*TRP + rl] = acc[mi][ni][hh*2+cc] + bias[n0+cl];
        }
        __syncthreads();
        int b = m0 >> nshift, nloc0 = m0 - (b << nshift);
        int cl = tid >> 1, half = tid & 1;
        uint32_t* Yw = (uint32_t*)Yout;
        uint32_t* dstrow = Yw + ((size_t)(b*HEADS + h)*DH + cl)*(size_t)(Nrows>>1) + (nloc0>>1);
        #pragma unroll
        for (int c2 = 0; c2 < 2; c2++){
            int chunk = half*2 + c2;
            const float* src = tr + cl*TRP + chunk*32;
            uint32_t wds[16];
            #pragma unroll
            for (int wd = 0; wd < 16; wd++){
                int j = wd >> 2, hi = (wd >> 1) & 1, s = wd & 1;
                int h0 = s*16 + hi*8 + 2*j;
                wds[wd] = packh2(src[h0], src[h0+1]);
            }
            uint32_t* dst = dstrow + chunk*16;
            #pragma unroll
            for (int qq = 0; qq < 4; qq++)
                ((uint4*)dst)[qq] = make_uint4(wds[qq*4], wds[qq*4+1], wds[qq*4+2], wds[qq*4+3]);
        }
    }
}

// ================= merged fused flash kernel (fp16 mma.sync) =================
__global__ void __launch_bounds__(256, 2)
flash_kernel(){
    __shared__ uint32_t sY[2][32*80];
    __shared__ uint32_t sP[2][128*16];
    const __half *X, *Y, *VT; __half* Mid; int M, Nk, mb;
    if (blockIdx.x < 4){ X=g_u; Y=g_v; VT=g_pT; Mid=g_Pmid; M=NQ; Nk=NK; mb=blockIdx.x; }
    else               { X=g_v; Y=g_u; VT=g_gT; Mid=g_Dmid; M=NK; Nk=NQ; mb=blockIdx.x-4; }
    const int bh = blockIdx.y;
    const int m0 = mb * 128;
    const int tid = threadIdx.x, w = tid >> 5, lane = tid & 31;
    const int g = lane >> 2, tq = lane & 3;
    const int Nk2 = Nk >> 1;
    const int NT = Nk / 32;
    const uint32_t* Xw = (const uint32_t*)(X + ((size_t)bh*M + m0)*DH);
    const uint32_t* Yw = (const uint32_t*)(Y + (size_t)bh*Nk*DH);
    const uint32_t* Vw = (const uint32_t*)(VT + (size_t)bh*DH*Nk);

    uint32_t syb[2], spb[2];
    syb[0] = (uint32_t)__cvta_generic_to_shared(&sY[0][0]);
    syb[1] = (uint32_t)__cvta_generic_to_shared(&sY[1][0]);
    spb[0] = (uint32_t)__cvta_generic_to_shared(&sP[0][0]);
    spb[1] = (uint32_t)__cvta_generic_to_shared(&sP[1][0]);

    // X A-fragments: registers, loaded once (perm32 gmem rows)
    uint4 xa[4], xb[4];
    {
        const uint32_t* Xr = Xw + (size_t)(w*16 + g)*64 + tq*4;
        #pragma unroll
        for (int kk2 = 0; kk2 < 4; kk2++){
            xa[kk2] = *(const uint4*)(Xr + kk2*16);
            xb[kk2] = *(const uint4*)(Xr + 8*64 + kk2*16);
        }
    }

    // issue tile 0
    {
        #pragma unroll
        for (int i = 0; i < 2; i++){
            int u = tid + i*256;
            int r = u >> 4, wq = u & 15;
            cpa16(syb[0] + (r*80 + wq*4)*4, Yw + (size_t)r*64 + wq*4);
        }
        #pragma unroll
        for (int i = 0; i < 2; i++){
            int u = tid + i*256;
            int r = u >> 2, q = u & 3;
            cpa16(spb[0] + (r*16 + q*4)*4, Vw + (size_t)r*Nk2 + q*4);
        }
        cpa_commit();
    }

    float acc[16][4] = {};
    float acc_rs[4] = {};
    int buf = 0;

    for (int kt = 0; kt < NT; kt++){
        cpa_wait0();
        __syncthreads();

        if (kt + 1 < NT){
            int nb = buf ^ 1;
            #pragma unroll
            for (int i = 0; i < 2; i++){
                int u = tid + i*256;
                int r = u >> 4, wq = u & 15;
                cpa16(syb[nb] + (r*80 + wq*4)*4, Yw + (size_t)((kt+1)*32 + r)*64 + wq*4);
            }
            #pragma unroll
            for (int i = 0; i < 2; i++){
                int u = tid + i*256;
                int r = u >> 2, q = u & 3;
                cpa16(spb[nb] + (r*16 + q*4)*4, Vw + (size_t)r*Nk2 + (kt+1)*16 + q*4);
            }
            cpa_commit();
        }

        const uint32_t* Ys = &sY[buf][0];
        const uint32_t* Ps = &sP[buf][0];

        // gemm1 + softmax, per-ni
        uint32_t eh[4][2];
        #pragma unroll
        for (int ni = 0; ni < 4; ni++){
            float cs[4] = {0.f, 0.f, 0.f, 0.f};
            #pragma unroll
            for (int kk2 = 0; kk2 < 4; kk2++){
                uint4 r = *(const uint4*)(Ys + (ni*8 + g)*80 + kk2*16 + tq*4);
                mma16h(cs, xa[kk2].x, xb[kk2].x, xa[kk2].z, xb[kk2].z, r.x, r.z);
                mma16h(cs, xa[kk2].y, xb[kk2].y, xa[kk2].w, xb[kk2].w, r.y, r.w);
            }
            float e0 = exp2f(cs[0]*SC2), e1 = exp2f(cs[1]*SC2);
            float e2 = exp2f(cs[2]*SC2), e3 = exp2f(cs[3]*SC2);
            eh[ni][0] = packh2(e0, e1);
            eh[ni][1] = packh2(e2, e3);
        }

        // rowsum via ones-mma (E @ 1)
        mma16h(acc_rs, eh[0][0], eh[0][1], eh[1][0], eh[1][1], ONESW, ONESW);
        mma16h(acc_rs, eh[2][0], eh[2][1], eh[3][0], eh[3][1], ONESW, ONESW);

        // gemm2: acc[16 x 128] per warp
        #pragma unroll
        for (int n2 = 0; n2 < 16; n2++){
            uint4 r = *(const uint4*)(Ps + (n2*8 + g)*16 + tq*4);
            mma16h(acc[n2], eh[0][0], eh[0][1], eh[1][0], eh[1][1], r.x, r.z);
            mma16h(acc[n2], eh[2][0], eh[2][1], eh[3][0], eh[3][1], r.y, r.w);
        }
        buf ^= 1;
    }

    // normalize + store perm32
    float i0 = 1.0f / acc_rs[0], i1 = 1.0f / acc_rs[2];
    int b = bh >> 3, h = bh & 7;
    int mg = m0 + w*16 + g;
    uint32_t* o0 = (uint32_t*)Mid + (((size_t)(b*M + mg    )*HEADS + h) << 6);
    uint32_t* o8 = (uint32_t*)Mid + (((size_t)(b*M + mg + 8)*HEADS + h) << 6);
    #pragma unroll
    for (int n2 = 0; n2 < 16; n2++){
        int col = n2*8 + 2*tq;
        int wrd = ((col >> 5) << 4) + perm_w(col & 31);
        o0[wrd] = packh2(acc[n2][0]*i0, acc[n2][1]*i0);
        o8[wrd] = packh2(acc[n2][2]*i1, acc[n2][3]*i1);
    }
}

// ================= merged output projection (fp16 cp.async GEMM) =================
__global__ void __launch_bounds__(256)
outproj_kernel(const float* __restrict__ bo1, const float* __restrict__ bo2,
               float* __restrict__ out){
    __shared__ uint32_t As[2][128*16];
    __shared__ uint32_t Bs[2][64*16];
    const int bx = blockIdx.x;
    const bool isD = (bx >= 64);
    const int m0 = (isD ? bx - 64 : bx) * 128;
    const int n0 = blockIdx.y * 64;
    const __half* Xh = isD ? g_Dmid : g_Pmid;
    const __half* Wh = isD ? g_Wo2h : g_Wo1h;
    const float* bias = isD ? bo2 : bo1;
    float* outp = out + (isD ? (size_t)BATCH*NQ*DH : 0);
    const int tid = threadIdx.x, w = tid >> 5, lane = tid & 31;
    const int g = lane >> 2, tq = lane & 3;
    const int wm = w >> 1, wn = w & 1;
    const uint32_t* Xw = (const uint32_t*)Xh + (size_t)m0*512;
    const uint32_t* Ww = (const uint32_t*)Wh + (size_t)n0*512;
    uint32_t sa = (uint32_t)__cvta_generic_to_shared(&As[0][0]);
    uint32_t sb = (uint32_t)__cvta_generic_to_shared(&Bs[0][0]);

    float c[2][4][4] = {};
    {
        #pragma unroll
        for (int i = 0; i < 2; i++){
            int u = tid + i*256; int r = u >> 2, q = u & 3;
            cpa16(sa + (r*16 + q*4)*4, Xw + (size_t)r*512 + q*4);
        }
        { int r = tid >> 2, q = tid & 3;
          cpa16(sb + (r*16 + q*4)*4, Ww + (size_t)r*512 + q*4); }
        cpa_commit();
    }

    int buf = 0;
    for (int kt = 0; kt < 32; kt++){
        cpa_wait0();
        __syncthreads();
        if (kt + 1 < 32){
            int nb = buf ^ 1;
            #pragma unroll
            for (int i = 0; i < 2; i++){
                int u = tid + i*256; int r = u >> 2, q = u & 3;
                cpa16(sa + (nb*2048 + r*16 + q*4)*4, Xw + (size_t)r*512 + (kt+1)*16 + q*4);
            }
            { int r = tid >> 2, q = tid & 3;
              cpa16(sb + (nb*1024 + r*16 + q*4)*4, Ww + (size_t)r*512 + (kt+1)*16 + q*4); }
            cpa_commit();
        }
        const uint32_t* A = &As[buf][0];
        const uint32_t* B = &Bs[buf][0];
        uint4 xa[2], xb[2];
        #pragma unroll
        for (int mi = 0; mi < 2; mi++){
            xa[mi] = *(const uint4*)(A + (wm*32+mi*16+g)*16 + tq*4);
            xb[mi] = *(const uint4*)(A + (wm*32+mi*16+g+8)*16 + tq*4);
        }
        #pragma unroll
        for (int ni = 0; ni < 4; ni++){
            uint4 bb = *(const uint4*)(B + (wn*32+ni*8+g)*16 + tq*4);
            #pragma unroll
            for (int mi = 0; mi < 2; mi++){
                mma16h(c[mi][ni], xa[mi].x, xb[mi].x, xa[mi].z, xb[mi].z, bb.x, bb.z);
                mma16h(c[mi][ni], xa[mi].y, xb[mi].y, xa[mi].w, xb[mi].w, bb.y, bb.w);
            }
        }
        buf ^= 1;
    }

    #pragma unroll
    for (int mi=0;mi<2;mi++)
    #pragma unroll
    for (int hh=0;hh<2;hh++)
    #pragma unroll
    for (int ni=0;ni<4;ni++)
    #pragma unroll
    for (int cc=0;cc<2;cc++){
        int row = m0 + wm*32 + mi*16 + g + hh*8;
        int col = n0 + wn*32 + ni*8 + tq*2 + cc;
        outp[((size_t)row << 7) + col] = c[mi][ni][hh*2+cc] + bias[col];
    }
}

// ---------------- launch ----------------
extern "C" void kernel_launch(void* const* d_in, const int* in_sizes, int n_in,
                              void* d_out, int out_size){
    const float* queries = (const float*)d_in[0];
    const float* keys    = (const float*)d_in[1];
    const float* Wq  = (const float*)d_in[2];
    const float* bq  = (const float*)d_in[3];
    const float* Wk  = (const float*)d_in[4];
    const float* bk  = (const float*)d_in[5];
    const float* Wp  = (const float*)d_in[6];
    const float* bp  = (const float*)d_in[7];
    const float* Wg  = (const float*)d_in[8];
    const float* bg  = (const float*)d_in[9];
    const float* Wo1 = (const float*)d_in[10];
    const float* bo1 = (const float*)d_in[11];
    const float* Wo2 = (const float*)d_in[12];
    const float* bo2 = (const float*)d_in[13];
    float* out = (float*)d_out;

    cudaFuncSetAttribute(proj_kernel, cudaFuncAttributeMaxDynamicSharedMemorySize, PRJ_BYTES);

    // fp32 -> fp16 perm32 for all inputs/weights
    conv_all_kernel<<<dim3(4096, 8), 256>>>(queries, keys, Wq, Wk, Wp, Wg, Wo1, Wo2);

    // input projections (u, v plain; pT, gT transposed)
    proj_kernel<<<dim3(192, 16), 256, PRJ_BYTES>>>(bq, bk, bp, bg);

    // both attention branches
    flash_kernel<<<dim3(12, BH), 256>>>();

    // output projections
    outproj_kernel<<<dim3(192, 2), 256>>>(bo1, bo2, out);
}

// round 10
// speedup vs baseline: 2.7699x; 1.0091x over previous
#include <cuda_runtime.h>
#include <cuda_fp16.h>
#include <cstdint>
#include <cstddef>

// ---------------- problem constants ----------------
#define BATCH 16
#define NQ    512
#define NK    1024
#define DH    128
#define HEADS 8
#define BH    (BATCH*HEADS)        // 128
#define SC2   0.12751741254364243f // (1/sqrt(128)) * log2(e)
#define ONESW 0x3C003C00u          // fp16 (1.0, 1.0)

#define TRP 136
#define PRJ_BYTES ((128*80 + 128*80)*4)   // 81920

// flash smem layout (words): Y 2x(64x80), P 2x(128x48)
#define FLY0 0
#define FLY1 (64*80)               // 5120
#define FLP0 (2*64*80)             // 10240
#define FLP1 (FLP0 + 128*48)       // 16384
#define FLW  (FLP1 + 128*48)       // 22528 words
#define FL_BYTES (FLW*4)           // 90112

// ---------------- device scratch (fp16, perm32 along K dim) ----------------
__device__ __half g_qh [8192*DH];
__device__ __half g_kh [16384*DH];
__device__ __half g_Wqh[1024*DH];
__device__ __half g_Wkh[1024*DH];
__device__ __half g_Wph[1024*DH];
__device__ __half g_Wgh[1024*DH];
__device__ __half g_u  [(size_t)BH*NQ*DH];
__device__ __half g_v  [(size_t)BH*NK*DH];
__device__ __half g_pT [(size_t)BH*DH*NK];
__device__ __half g_gT [(size_t)BH*DH*NQ];
__device__ __half g_Pmid[(size_t)BATCH*NQ*HEADS*DH];
__device__ __half g_Dmid[(size_t)BATCH*NK*HEADS*DH];
__device__ __half g_Wo1h[128*1024];
__device__ __half g_Wo2h[128*1024];

// ---------------- helpers ----------------
__device__ __forceinline__ uint32_t packh2(float a, float b){
    __half2 h = __floats2half2_rn(a, b);
    return *reinterpret_cast<uint32_t*>(&h);
}
__device__ __forceinline__ void mma16h(float (&c)[4], uint32_t a0, uint32_t a1, uint32_t a2, uint32_t a3,
                                       uint32_t b0, uint32_t b1){
    asm volatile("mma.sync.aligned.m16n8k16.row.col.f32.f16.f16.f32 "
        "{%0,%1,%2,%3}, {%4,%5,%6,%7}, {%8,%9}, {%0,%1,%2,%3};"
        : "+f"(c[0]),"+f"(c[1]),"+f"(c[2]),"+f"(c[3])
        : "r"(a0),"r"(a1),"r"(a2),"r"(a3), "r"(b0),"r"(b1));
}
__device__ __forceinline__ void cpa16(uint32_t dst_shared, const void* src){
    asm volatile("cp.async.cg.shared.global [%0], [%1], 16;" :: "r"(dst_shared), "l"(src));
}
__device__ __forceinline__ void cpa_commit(){ asm volatile("cp.async.commit_group;"); }
__device__ __forceinline__ void cpa_wait0(){ asm volatile("cp.async.wait_group 0;"); }
__device__ __forceinline__ void cpa_wait1(){ asm volatile("cp.async.wait_group 1;"); }

// perm32: word w of a 32-half chunk = j*4+hi*2+s holds halves (s*16+hi*8+2j, +1)
__device__ __forceinline__ int perm_w(int h32){
    int s = (h32 >> 4) & 1, hi = (h32 >> 3) & 1, j = (h32 & 7) >> 1;
    return j*4 + hi*2 + s;
}

// ================= conversion kernel: fp32 -> fp16 perm32 =================
__global__ void __launch_bounds__(256)
conv_all_kernel(const float* __restrict__ q, const float* __restrict__ k,
                const float* __restrict__ Wq, const float* __restrict__ Wk,
                const float* __restrict__ Wp, const float* __restrict__ Wg,
                const float* __restrict__ Wo1, const float* __restrict__ Wo2){
    int t = blockIdx.x*256 + threadIdx.x;
    int seg = blockIdx.y;
    const float* src; uint32_t* dst; int nwords;
    switch (seg){
        case 0: src = q;   dst = (uint32_t*)g_qh;  nwords = 8192*64;  break;
        case 1: src = k;   dst = (uint32_t*)g_kh;  nwords = 16384*64; break;
        case 2: src = Wq;  dst = (uint32_t*)g_Wqh; nwords = 1024*64;  break;
        case 3: src = Wk;  dst = (uint32_t*)g_Wkh; nwords = 1024*64;  break;
        case 4: src = Wp;  dst = (uint32_t*)g_Wph; nwords = 1024*64;  break;
        case 5: src = Wg;  dst = (uint32_t*)g_Wgh; nwords = 1024*64;  break;
        case 6: src = Wo1; dst = (uint32_t*)g_Wo1h; nwords = 128*512; break;
        default:src = Wo2; dst = (uint32_t*)g_Wo2h; nwords = 128*512; break;
    }
    if (t >= nwords) return;
    int r, w9, rowfloats;
    if (seg < 6){ r = t >> 6; w9 = t & 63;  rowfloats = 128;  }
    else        { r = t >> 9; w9 = t & 511; rowfloats = 1024; }
    int chunk = w9 >> 4, wd = w9 & 15;
    int j = wd >> 2, hi = (wd >> 1) & 1, s = wd & 1;
    int k0 = chunk*32 + s*16 + hi*8 + 2*j;
    const float* sp = src + (size_t)r*rowfloats + k0;
    dst[t] = packh2(sp[0], sp[1]);
}

// ================= input projections (fp16 cp.async GEMM) =================
__global__ void __launch_bounds__(256)
proj_kernel(const float* __restrict__ bq, const float* __restrict__ bk,
            const float* __restrict__ bp, const float* __restrict__ bg){
    extern __shared__ uint32_t smw[];
    const int bx = blockIdx.x;
    const bool isK = (bx >= 64);
    const int m0 = (isK ? bx - 64 : bx) * 128;
    const int trans = blockIdx.y >> 3;
    const int n0 = (blockIdx.y & 7) * 128;
    const __half* Xh  = isK ? g_kh : g_qh;
    const __half* Wh  = trans ? (isK ? g_Wph : g_Wgh) : (isK ? g_Wkh : g_Wqh);
    const float* bias = trans ? (isK ? bp : bg) : (isK ? bk : bq);
    __half* Yout      = trans ? (isK ? g_pT : g_gT) : (isK ? g_v : g_u);
    const int Nrows   = isK ? NK : NQ;
    const int nshift  = isK ? 10 : 9;
    const int tid = threadIdx.x, w = tid >> 5, lane = tid & 31;
    const int g = lane >> 2, tq = lane & 3;
    const int wm = w >> 1, wn = w & 1;

    uint32_t sx = (uint32_t)__cvta_generic_to_shared(smw);
    uint32_t sw = sx + 10240*4;
    const uint32_t* Xw = (const uint32_t*)Xh + (size_t)m0*64;
    const uint32_t* Ww = (const uint32_t*)Wh + (size_t)n0*64;
    #pragma unroll
    for (int i = 0; i < 8; i++){
        int id = tid + i*256;
        int r = id >> 4, wq = id & 15;
        cpa16(sx + (r*80 + wq*4)*4, Xw + (size_t)r*64 + wq*4);
        cpa16(sw + (r*80 + wq*4)*4, Ww + (size_t)r*64 + wq*4);
    }
    cpa_commit();
    cpa_wait0();
    __syncthreads();

    float acc[2][8][4] = {};
    const uint32_t* Xs = smw;
    const uint32_t* Ws = smw + 10240;
    #pragma unroll
    for (int kk = 0; kk < 4; kk++){
        uint4 xa[2], xb[2];
        #pragma unroll
        for (int mi = 0; mi < 2; mi++){
            xa[mi] = *(const uint4*)(Xs + (wm*32+mi*16+g)*80 + kk*16 + tq*4);
            xb[mi] = *(const uint4*)(Xs + (wm*32+mi*16+g+8)*80 + kk*16 + tq*4);
        }
        #pragma unroll
        for (int ni = 0; ni < 8; ni++){
            uint4 bb = *(const uint4*)(Ws + (wn*64+ni*8+g)*80 + kk*16 + tq*4);
            #pragma unroll
            for (int mi = 0; mi < 2; mi++){
                mma16h(acc[mi][ni], xa[mi].x, xb[mi].x, xa[mi].z, xb[mi].z, bb.x, bb.z);
                mma16h(acc[mi][ni], xa[mi].y, xb[mi].y, xa[mi].w, xb[mi].w, bb.y, bb.w);
            }
        }
    }
    __syncthreads();

    const int h = n0 >> 7;
    if (!trans){
        uint32_t* Yw = (uint32_t*)Yout;
        #pragma unroll
        for (int mi = 0; mi < 2; mi++)
        #pragma unroll
        for (int hh = 0; hh < 2; hh++)
        #pragma unroll
        for (int ni = 0; ni < 8; ni++){
            int row = m0 + wm*32 + mi*16 + g + hh*8;
            int d = wn*64 + ni*8 + tq*2;
            int b = row >> nshift, n = row - (b << nshift);
            int wrd = ((d >> 5) << 4) + perm_w(d & 31);
            Yw[(size_t)((b*HEADS + h)*Nrows + n)*64 + wrd] =
                packh2(acc[mi][ni][hh*2] + bias[n0+d], acc[mi][ni][hh*2+1] + bias[n0+d+1]);
        }
    } else {
        float* tr = (float*)smw;
        #pragma unroll
        for (int mi = 0; mi < 2; mi++)
        #pragma unroll
        for (int hh = 0; hh < 2; hh++)
        #pragma unroll
        for (int ni = 0; ni < 8; ni++)
        #pragma unroll
        for (int cc = 0; cc < 2; cc++){
            int rl = wm*32 + mi*16 + g + hh*8;
            int cl = wn*64 + ni*8 + tq*2 + cc;
            tr[cl*TRP + rl] = acc[mi][ni][hh*2+cc] + bias[n0+cl];
        }
        __syncthreads();
        int b = m0 >> nshift, nloc0 = m0 - (b << nshift);
        int cl = tid >> 1, half = tid & 1;
        uint32_t* Yw = (uint32_t*)Yout;
        uint32_t* dstrow = Yw + ((size_t)(b*HEADS + h)*DH + cl)*(size_t)(Nrows>>1) + (nloc0>>1);
        #pragma unroll
        for (int c2 = 0; c2 < 2; c2++){
            int chunk = half*2 + c2;
            const float* src = tr + cl*TRP + chunk*32;
            uint32_t wds[16];
            #pragma unroll
            for (int wd = 0; wd < 16; wd++){
                int j = wd >> 2, hi = (wd >> 1) & 1, s = wd & 1;
                int h0 = s*16 + hi*8 + 2*j;
                wds[wd] = packh2(src[h0], src[h0+1]);
            }
            uint32_t* dst = dstrow + chunk*16;
            #pragma unroll
            for (int qq = 0; qq < 4; qq++)
                ((uint4*)dst)[qq] = make_uint4(wds[qq*4], wds[qq*4+1], wds[qq*4+2], wds[qq*4+3]);
        }
    }
}

// ================= merged fused flash kernel (fp16 mma.sync, 64-key stages) =================
__global__ void __launch_bounds__(256, 2)
flash_kernel(){
    extern __shared__ uint32_t smw[];
    const __half *X, *Y, *VT; __half* Mid; int M, Nk, mb;
    if (blockIdx.x < 4){ X=g_u; Y=g_v; VT=g_pT; Mid=g_Pmid; M=NQ; Nk=NK; mb=blockIdx.x; }
    else               { X=g_v; Y=g_u; VT=g_gT; Mid=g_Dmid; M=NK; Nk=NQ; mb=blockIdx.x-4; }
    const int bh = blockIdx.y;
    const int m0 = mb * 128;
    const int tid = threadIdx.x, w = tid >> 5, lane = tid & 31;
    const int g = lane >> 2, tq = lane & 3;
    const int Nk2 = Nk >> 1;
    const int NT = Nk >> 6;                  // 64-key stages
    const uint32_t* Xw = (const uint32_t*)(X + ((size_t)bh*M + m0)*DH);
    const uint32_t* Yw = (const uint32_t*)(Y + (size_t)bh*Nk*DH);
    const uint32_t* Vw = (const uint32_t*)(VT + (size_t)bh*DH*Nk);
    uint32_t sbase = (uint32_t)__cvta_generic_to_shared(smw);

    // X A-fragments: registers, loaded once (perm32 gmem rows)
    uint4 xa[4], xb[4];
    {
        const uint32_t* Xr = Xw + (size_t)(w*16 + g)*64 + tq*4;
        #pragma unroll
        for (int kk2 = 0; kk2 < 4; kk2++){
            xa[kk2] = *(const uint4*)(Xr + kk2*16);
            xb[kk2] = *(const uint4*)(Xr + 8*64 + kk2*16);
        }
    }

    // stage loaders: Y 64 rows x 16 words, P 128 rows x 32 words (stride 48)
    const int yr = tid >> 4, ywq = tid & 15;     // helper decomposition per 256-thread pass
    const int pr2 = tid >> 3, pch = tid & 7;

    // issue stage 0
    {
        #pragma unroll
        for (int i = 0; i < 4; i++){
            int r = yr + i*16;
            cpa16(sbase + (FLY0 + r*80 + ywq*4)*4, Yw + (size_t)r*64 + ywq*4);
        }
        #pragma unroll
        for (int i = 0; i < 4; i++){
            int r = pr2 + i*32;
            cpa16(sbase + (FLP0 + r*48 + pch*4)*4, Vw + (size_t)r*Nk2 + pch*4);
        }
        cpa_commit();
    }

    float acc[16][4] = {};
    float acc_rs[4] = {};
    int buf = 0;

    for (int kt = 0; kt < NT; kt++){
        cpa_wait0();
        __syncthreads();

        if (kt + 1 < NT){
            int yb = buf ? FLY0 : FLY1;
            int pb = buf ? FLP0 : FLP1;
            #pragma unroll
            for (int i = 0; i < 4; i++){
                int r = yr + i*16;
                cpa16(sbase + (yb + r*80 + ywq*4)*4, Yw + (size_t)((kt+1)*64 + r)*64 + ywq*4);
            }
            #pragma unroll
            for (int i = 0; i < 4; i++){
                int r = pr2 + i*32;
                cpa16(sbase + (pb + r*48 + pch*4)*4, Vw + (size_t)r*Nk2 + (kt+1)*32 + pch*4);
            }
            cpa_commit();
        }

        const uint32_t* Yb = smw + (buf ? FLY1 : FLY0);
        const uint32_t* Pb = smw + (buf ? FLP1 : FLP0);

        #pragma unroll
        for (int sub = 0; sub < 2; sub++){
            const uint32_t* Ys = Yb + sub*32*80;

            // gemm1 + softmax (per-ni)
            uint32_t eh[4][2];
            #pragma unroll
            for (int ni = 0; ni < 4; ni++){
                float cs[4] = {0.f, 0.f, 0.f, 0.f};
                #pragma unroll
                for (int kk2 = 0; kk2 < 4; kk2++){
                    uint4 r = *(const uint4*)(Ys + (ni*8 + g)*80 + kk2*16 + tq*4);
                    mma16h(cs, xa[kk2].x, xb[kk2].x, xa[kk2].z, xb[kk2].z, r.x, r.z);
                    mma16h(cs, xa[kk2].y, xb[kk2].y, xa[kk2].w, xb[kk2].w, r.y, r.w);
                }
                float e0 = exp2f(cs[0]*SC2), e1 = exp2f(cs[1]*SC2);
                float e2 = exp2f(cs[2]*SC2), e3 = exp2f(cs[3]*SC2);
                eh[ni][0] = packh2(e0, e1);
                eh[ni][1] = packh2(e2, e3);
            }

            // rowsum via ones-mma
            mma16h(acc_rs, eh[0][0], eh[0][1], eh[1][0], eh[1][1], ONESW, ONESW);
            mma16h(acc_rs, eh[2][0], eh[2][1], eh[3][0], eh[3][1], ONESW, ONESW);

            // gemm2
            #pragma unroll
            for (int n2 = 0; n2 < 16; n2++){
                uint4 r = *(const uint4*)(Pb + (n2*8 + g)*48 + sub*16 + tq*4);
                mma16h(acc[n2], eh[0][0], eh[0][1], eh[1][0], eh[1][1], r.x, r.z);
                mma16h(acc[n2], eh[2][0], eh[2][1], eh[3][0], eh[3][1], r.y, r.w);
            }
        }
        buf ^= 1;
    }

    // normalize + store perm32
    float i0 = 1.0f / acc_rs[0], i1 = 1.0f / acc_rs[2];
    int b = bh >> 3, h = bh & 7;
    int mg = m0 + w*16 + g;
    uint32_t* o0 = (uint32_t*)Mid + (((size_t)(b*M + mg    )*HEADS + h) << 6);
    uint32_t* o8 = (uint32_t*)Mid + (((size_t)(b*M + mg + 8)*HEADS + h) << 6);
    #pragma unroll
    for (int n2 = 0; n2 < 16; n2++){
        int col = n2*8 + 2*tq;
        int wrd = ((col >> 5) << 4) + perm_w(col & 31);
        o0[wrd] = packh2(acc[n2][0]*i0, acc[n2][1]*i0);
        o8[wrd] = packh2(acc[n2][2]*i1, acc[n2][3]*i1);
    }
}

// ================= merged output projection (fp16 cp.async, 3-stage) =================
__global__ void __launch_bounds__(256)
outproj_kernel(const float* __restrict__ bo1, const float* __restrict__ bo2,
               float* __restrict__ out){
    __shared__ uint32_t As[3][128*16];
    __shared__ uint32_t Bs[3][64*16];
    const int bx = blockIdx.x;
    const bool isD = (bx >= 64);
    const int m0 = (isD ? bx - 64 : bx) * 128;
    const int n0 = blockIdx.y * 64;
    const __half* Xh = isD ? g_Dmid : g_Pmid;
    const __half* Wh = isD ? g_Wo2h : g_Wo1h;
    const float* bias = isD ? bo2 : bo1;
    float* outp = out + (isD ? (size_t)BATCH*NQ*DH : 0);
    const int tid = threadIdx.x, w = tid >> 5, lane = tid & 31;
    const int g = lane >> 2, tq = lane & 3;
    const int wm = w >> 1, wn = w & 1;
    const uint32_t* Xw = (const uint32_t*)Xh + (size_t)m0*512;
    const uint32_t* Ww = (const uint32_t*)Wh + (size_t)n0*512;
    uint32_t sa = (uint32_t)__cvta_generic_to_shared(&As[0][0]);
    uint32_t sb = (uint32_t)__cvta_generic_to_shared(&Bs[0][0]);
    const int ar = tid >> 2, aq = tid & 3;

    auto issue = [&](int kt, int st){
        #pragma unroll
        for (int i = 0; i < 2; i++){
            int r = ar + i*64;
            cpa16(sa + (st*2048 + r*16 + aq*4)*4, Xw + (size_t)r*512 + kt*16 + aq*4);
        }
        if (ar < 64)
            cpa16(sb + (st*1024 + ar*16 + aq*4)*4, Ww + (size_t)ar*512 + kt*16 + aq*4);
        cpa_commit();
    };

    float c[2][4][4] = {};
    issue(0, 0);
    issue(1, 1);

    for (int kt = 0; kt < 32; kt++){
        if (kt < 31) cpa_wait1(); else cpa_wait0();
        __syncthreads();
        if (kt + 2 < 32) issue(kt+2, (kt+2) % 3);

        const uint32_t* A = &As[kt % 3][0];
        const uint32_t* B = &Bs[kt % 3][0];
        uint4 xa[2], xb[2];
        #pragma unroll
        for (int mi = 0; mi < 2; mi++){
            xa[mi] = *(const uint4*)(A + (wm*32+mi*16+g)*16 + tq*4);
            xb[mi] = *(const uint4*)(A + (wm*32+mi*16+g+8)*16 + tq*4);
        }
        #pragma unroll
        for (int ni = 0; ni < 4; ni++){
            uint4 bb = *(const uint4*)(B + (wn*32+ni*8+g)*16 + tq*4);
            #pragma unroll
            for (int mi = 0; mi < 2; mi++){
                mma16h(c[mi][ni], xa[mi].x, xb[mi].x, xa[mi].z, xb[mi].z, bb.x, bb.z);
                mma16h(c[mi][ni], xa[mi].y, xb[mi].y, xa[mi].w, xb[mi].w, bb.y, bb.w);
            }
        }
    }

    #pragma unroll
    for (int mi=0;mi<2;mi++)
    #pragma unroll
    for (int hh=0;hh<2;hh++)
    #pragma unroll
    for (int ni=0;ni<4;ni++)
    #pragma unroll
    for (int cc=0;cc<2;cc++){
        int row = m0 + wm*32 + mi*16 + g + hh*8;
        int col = n0 + wn*32 + ni*8 + tq*2 + cc;
        outp[((size_t)row << 7) + col] = c[mi][ni][hh*2+cc] + bias[col];
    }
}

// ---------------- launch ----------------
extern "C" void kernel_launch(void* const* d_in, const int* in_sizes, int n_in,
                              void* d_out, int out_size){
    const float* queries = (const float*)d_in[0];
    const float* keys    = (const float*)d_in[1];
    const float* Wq  = (const float*)d_in[2];
    const float* bq  = (const float*)d_in[3];
    const float* Wk  = (const float*)d_in[4];
    const float* bk  = (const float*)d_in[5];
    const float* Wp  = (const float*)d_in[6];
    const float* bp  = (const float*)d_in[7];
    const float* Wg  = (const float*)d_in[8];
    const float* bg  = (const float*)d_in[9];
    const float* Wo1 = (const float*)d_in[10];
    const float* bo1 = (const float*)d_in[11];
    const float* Wo2 = (const float*)d_in[12];
    const float* bo2 = (const float*)d_in[13];
    float* out = (float*)d_out;

    cudaFuncSetAttribute(proj_kernel,  cudaFuncAttributeMaxDynamicSharedMemorySize, PRJ_BYTES);
    cudaFuncSetAttribute(flash_kernel, cudaFuncAttributeMaxDynamicSharedMemorySize, FL_BYTES);

    conv_all_kernel<<<dim3(4096, 8), 256>>>(queries, keys, Wq, Wk, Wp, Wg, Wo1, Wo2);

    proj_kernel<<<dim3(192, 16), 256, PRJ_BYTES>>>(bq, bk, bp, bg);

    flash_kernel<<<dim3(12, BH), 256, FL_BYTES>>>();

    outproj_kernel<<<dim3(192, 2), 256>>>(bo1, bo2, out);
}

// round 11
// speedup vs baseline: 2.8307x; 1.0219x over previous
#include <cuda_runtime.h>
#include <cuda_fp16.h>
#include <cstdint>
#include <cstddef>

// ---------------- problem constants ----------------
#define BATCH 16
#define NQ    512
#define NK    1024
#define DH    128
#define HEADS 8
#define BH    (BATCH*HEADS)        // 128
#define SC2   0.12751741254364243f // (1/sqrt(128)) * log2(e)  -- folded into Wq/bq
#define ONESW 0x3C003C00u          // fp16 (1.0, 1.0)

#define TRP 136
#define PRJ_BYTES ((128*80 + 128*80)*4)   // 81920

// flash smem layout (words): Y 2x(64x80), P 2x(128x48)
#define FLY0 0
#define FLY1 (64*80)
#define FLP0 (2*64*80)
#define FLP1 (FLP0 + 128*48)
#define FLW  (FLP1 + 128*48)
#define FL_BYTES (FLW*4)           // 90112

// ---------------- device scratch (fp16, perm32 along K dim) ----------------
__device__ __half g_qh [8192*DH];
__device__ __half g_kh [16384*DH];
__device__ __half g_Wqh[1024*DH];
__device__ __half g_Wkh[1024*DH];
__device__ __half g_Wph[1024*DH];
__device__ __half g_Wgh[1024*DH];
__device__ __half g_u  [(size_t)BH*NQ*DH];      // pre-scaled by SC2
__device__ __half g_v  [(size_t)BH*NK*DH];
__device__ __half g_pT [(size_t)BH*DH*NK];
__device__ __half g_gT [(size_t)BH*DH*NQ];
__device__ __half g_Pmid[(size_t)BATCH*NQ*HEADS*DH];
__device__ __half g_Dmid[(size_t)BATCH*NK*HEADS*DH];
__device__ __half g_Wo1h[128*1024];
__device__ __half g_Wo2h[128*1024];

// ---------------- helpers ----------------
__device__ __forceinline__ uint32_t packh2(float a, float b){
    __half2 h = __floats2half2_rn(a, b);
    return *reinterpret_cast<uint32_t*>(&h);
}
__device__ __forceinline__ uint32_t ex2h2(uint32_t x){
    uint32_t r;
    asm("ex2.approx.f16x2 %0, %1;" : "=r"(r) : "r"(x));
    return r;
}
__device__ __forceinline__ void mma16h(float (&c)[4], uint32_t a0, uint32_t a1, uint32_t a2, uint32_t a3,
                                       uint32_t b0, uint32_t b1){
    asm volatile("mma.sync.aligned.m16n8k16.row.col.f32.f16.f16.f32 "
        "{%0,%1,%2,%3}, {%4,%5,%6,%7}, {%8,%9}, {%0,%1,%2,%3};"
        : "+f"(c[0]),"+f"(c[1]),"+f"(c[2]),"+f"(c[3])
        : "r"(a0),"r"(a1),"r"(a2),"r"(a3), "r"(b0),"r"(b1));
}
__device__ __forceinline__ void cpa16(uint32_t dst_shared, const void* src){
    asm volatile("cp.async.cg.shared.global [%0], [%1], 16;" :: "r"(dst_shared), "l"(src));
}
__device__ __forceinline__ void cpa_commit(){ asm volatile("cp.async.commit_group;"); }
__device__ __forceinline__ void cpa_wait0(){ asm volatile("cp.async.wait_group 0;"); }

// perm32: word w of a 32-half chunk = j*4+hi*2+s holds halves (s*16+hi*8+2j, +1)
__device__ __forceinline__ int perm_w(int h32){
    int s = (h32 >> 4) & 1, hi = (h32 >> 3) & 1, j = (h32 & 7) >> 1;
    return j*4 + hi*2 + s;
}

// ================= conversion kernel: fp32 -> fp16 perm32 =================
// seg 2 (Wq) pre-scaled by SC2 so S arrives in log2-domain.
__global__ void __launch_bounds__(256)
conv_all_kernel(const float* __restrict__ q, const float* __restrict__ k,
                const float* __restrict__ Wq, const float* __restrict__ Wk,
                const float* __restrict__ Wp, const float* __restrict__ Wg,
                const float* __restrict__ Wo1, const float* __restrict__ Wo2){
    int t = blockIdx.x*256 + threadIdx.x;
    int seg = blockIdx.y;
    const float* src; uint32_t* dst; int nwords;
    switch (seg){
        case 0: src = q;   dst = (uint32_t*)g_qh;  nwords = 8192*64;  break;
        case 1: src = k;   dst = (uint32_t*)g_kh;  nwords = 16384*64; break;
        case 2: src = Wq;  dst = (uint32_t*)g_Wqh; nwords = 1024*64;  break;
        case 3: src = Wk;  dst = (uint32_t*)g_Wkh; nwords = 1024*64;  break;
        case 4: src = Wp;  dst = (uint32_t*)g_Wph; nwords = 1024*64;  break;
        case 5: src = Wg;  dst = (uint32_t*)g_Wgh; nwords = 1024*64;  break;
        case 6: src = Wo1; dst = (uint32_t*)g_Wo1h; nwords = 128*512; break;
        default:src = Wo2; dst = (uint32_t*)g_Wo2h; nwords = 128*512; break;
    }
    if (t >= nwords) return;
    int r, w9, rowfloats;
    if (seg < 6){ r = t >> 6; w9 = t & 63;  rowfloats = 128;  }
    else        { r = t >> 9; w9 = t & 511; rowfloats = 1024; }
    int chunk = w9 >> 4, wd = w9 & 15;
    int j = wd >> 2, hi = (wd >> 1) & 1, s = wd & 1;
    int k0 = chunk*32 + s*16 + hi*8 + 2*j;
    const float* sp = src + (size_t)r*rowfloats + k0;
    float sc = (seg == 2) ? SC2 : 1.0f;
    dst[t] = packh2(sp[0]*sc, sp[1]*sc);
}

// ================= input projections (fp16 cp.async GEMM) =================
__global__ void __launch_bounds__(256)
proj_kernel(const float* __restrict__ bq, const float* __restrict__ bk,
            const float* __restrict__ bp, const float* __restrict__ bg){
    extern __shared__ uint32_t smw[];
    const int bx = blockIdx.x;
    const bool isK = (bx >= 64);
    const int m0 = (isK ? bx - 64 : bx) * 128;
    const int trans = blockIdx.y >> 3;
    const int n0 = (blockIdx.y & 7) * 128;
    const __half* Xh  = isK ? g_kh : g_qh;
    const __half* Wh  = trans ? (isK ? g_Wph : g_Wgh) : (isK ? g_Wkh : g_Wqh);
    const float* bias = trans ? (isK ? bp : bg) : (isK ? bk : bq);
    __half* Yout      = trans ? (isK ? g_pT : g_gT) : (isK ? g_v : g_u);
    const float bsc   = (!isK && !trans) ? SC2 : 1.0f;   // u gets scaled bias
    const int Nrows   = isK ? NK : NQ;
    const int nshift  = isK ? 10 : 9;
    const int tid = threadIdx.x, w = tid >> 5, lane = tid & 31;
    const int g = lane >> 2, tq = lane & 3;
    const int wm = w >> 1, wn = w & 1;

    uint32_t sx = (uint32_t)__cvta_generic_to_shared(smw);
    uint32_t sw = sx + 10240*4;
    const uint32_t* Xw = (const uint32_t*)Xh + (size_t)m0*64;
    const uint32_t* Ww = (const uint32_t*)Wh + (size_t)n0*64;
    #pragma unroll
    for (int i = 0; i < 8; i++){
        int id = tid + i*256;
        int r = id >> 4, wq = id & 15;
        cpa16(sx + (r*80 + wq*4)*4, Xw + (size_t)r*64 + wq*4);
        cpa16(sw + (r*80 + wq*4)*4, Ww + (size_t)r*64 + wq*4);
    }
    cpa_commit();
    cpa_wait0();
    __syncthreads();

    float acc[2][8][4] = {};
    const uint32_t* Xs = smw;
    const uint32_t* Ws = smw + 10240;
    #pragma unroll
    for (int kk = 0; kk < 4; kk++){
        uint4 xa[2], xb[2];
        #pragma unroll
        for (int mi = 0; mi < 2; mi++){
            xa[mi] = *(const uint4*)(Xs + (wm*32+mi*16+g)*80 + kk*16 + tq*4);
            xb[mi] = *(const uint4*)(Xs + (wm*32+mi*16+g+8)*80 + kk*16 + tq*4);
        }
        #pragma unroll
        for (int ni = 0; ni < 8; ni++){
            uint4 bb = *(const uint4*)(Ws + (wn*64+ni*8+g)*80 + kk*16 + tq*4);
            #pragma unroll
            for (int mi = 0; mi < 2; mi++){
                mma16h(acc[mi][ni], xa[mi].x, xb[mi].x, xa[mi].z, xb[mi].z, bb.x, bb.z);
                mma16h(acc[mi][ni], xa[mi].y, xb[mi].y, xa[mi].w, xb[mi].w, bb.y, bb.w);
            }
        }
    }
    __syncthreads();

    const int h = n0 >> 7;
    if (!trans){
        uint32_t* Yw = (uint32_t*)Yout;
        #pragma unroll
        for (int mi = 0; mi < 2; mi++)
        #pragma unroll
        for (int hh = 0; hh < 2; hh++)
        #pragma unroll
        for (int ni = 0; ni < 8; ni++){
            int row = m0 + wm*32 + mi*16 + g + hh*8;
            int d = wn*64 + ni*8 + tq*2;
            int b = row >> nshift, n = row - (b << nshift);
            int wrd = ((d >> 5) << 4) + perm_w(d & 31);
            Yw[(size_t)((b*HEADS + h)*Nrows + n)*64 + wrd] =
                packh2(acc[mi][ni][hh*2] + bias[n0+d]*bsc, acc[mi][ni][hh*2+1] + bias[n0+d+1]*bsc);
        }
    } else {
        float* tr = (float*)smw;
        #pragma unroll
        for (int mi = 0; mi < 2; mi++)
        #pragma unroll
        for (int hh = 0; hh < 2; hh++)
        #pragma unroll
        for (int ni = 0; ni < 8; ni++)
        #pragma unroll
        for (int cc = 0; cc < 2; cc++){
            int rl = wm*32 + mi*16 + g + hh*8;
            int cl = wn*64 + ni*8 + tq*2 + cc;
            tr[cl*TRP + rl] = acc[mi][ni][hh*2+cc] + bias[n0+cl];
        }
        __syncthreads();
        int b = m0 >> nshift, nloc0 = m0 - (b << nshift);
        int cl = tid >> 1, half = tid & 1;
        uint32_t* Yw = (uint32_t*)Yout;
        uint32_t* dstrow = Yw + ((size_t)(b*HEADS + h)*DH + cl)*(size_t)(Nrows>>1) + (nloc0>>1);
        #pragma unroll
        for (int c2 = 0; c2 < 2; c2++){
            int chunk = half*2 + c2;
            const float* src = tr + cl*TRP + chunk*32;
            uint32_t wds[16];
            #pragma unroll
            for (int wd = 0; wd < 16; wd++){
                int j = wd >> 2, hi = (wd >> 1) & 1, s = wd & 1;
                int h0 = s*16 + hi*8 + 2*j;
                wds[wd] = packh2(src[h0], src[h0+1]);
            }
            uint32_t* dst = dstrow + chunk*16;
            #pragma unroll
            for (int qq = 0; qq < 4; qq++)
                ((uint4*)dst)[qq] = make_uint4(wds[qq*4], wds[qq*4+1], wds[qq*4+2], wds[qq*4+3]);
        }
    }
}

// ================= merged fused flash kernel (fp16 mma.sync, 64-key stages) =================
__global__ void __launch_bounds__(256, 2)
flash_kernel(){
    extern __shared__ uint32_t smw[];
    const __half *X, *Y, *VT; __half* Mid; int M, Nk, mb;
    if (blockIdx.x < 4){ X=g_u; Y=g_v; VT=g_pT; Mid=g_Pmid; M=NQ; Nk=NK; mb=blockIdx.x; }
    else               { X=g_v; Y=g_u; VT=g_gT; Mid=g_Dmid; M=NK; Nk=NQ; mb=blockIdx.x-4; }
    const int bh = blockIdx.y;
    const int m0 = mb * 128;
    const int tid = threadIdx.x, w = tid >> 5, lane = tid & 31;
    const int g = lane >> 2, tq = lane & 3;
    const int Nk2 = Nk >> 1;
    const int NT = Nk >> 6;
    const uint32_t* Xw = (const uint32_t*)(X + ((size_t)bh*M + m0)*DH);
    const uint32_t* Yw = (const uint32_t*)(Y + (size_t)bh*Nk*DH);
    const uint32_t* Vw = (const uint32_t*)(VT + (size_t)bh*DH*Nk);
    uint32_t sbase = (uint32_t)__cvta_generic_to_shared(smw);

    // X A-fragments: registers, loaded once
    uint4 xa[4], xb[4];
    {
        const uint32_t* Xr = Xw + (size_t)(w*16 + g)*64 + tq*4;
        #pragma unroll
        for (int kk2 = 0; kk2 < 4; kk2++){
            xa[kk2] = *(const uint4*)(Xr + kk2*16);
            xb[kk2] = *(const uint4*)(Xr + 8*64 + kk2*16);
        }
    }

    const int yr = tid >> 4, ywq = tid & 15;
    const int pr2 = tid >> 3, pch = tid & 7;

    // issue stage 0
    {
        #pragma unroll
        for (int i = 0; i < 4; i++){
            int r = yr + i*16;
            cpa16(sbase + (FLY0 + r*80 + ywq*4)*4, Yw + (size_t)r*64 + ywq*4);
        }
        #pragma unroll
        for (int i = 0; i < 4; i++){
            int r = pr2 + i*32;
            cpa16(sbase + (FLP0 + r*48 + pch*4)*4, Vw + (size_t)r*Nk2 + pch*4);
        }
        cpa_commit();
    }

    float acc[16][4] = {};
    float acc_rs[4] = {};
    int buf = 0;

    for (int kt = 0; kt < NT; kt++){
        cpa_wait0();
        __syncthreads();

        if (kt + 1 < NT){
            int yb = buf ? FLY0 : FLY1;
            int pb = buf ? FLP0 : FLP1;
            #pragma unroll
            for (int i = 0; i < 4; i++){
                int r = yr + i*16;
                cpa16(sbase + (yb + r*80 + ywq*4)*4, Yw + (size_t)((kt+1)*64 + r)*64 + ywq*4);
            }
            #pragma unroll
            for (int i = 0; i < 4; i++){
                int r = pr2 + i*32;
                cpa16(sbase + (pb + r*48 + pch*4)*4, Vw + (size_t)r*Nk2 + (kt+1)*32 + pch*4);
            }
            cpa_commit();
        }

        const uint32_t* Yb = smw + (buf ? FLY1 : FLY0);
        const uint32_t* Pb = smw + (buf ? FLP1 : FLP0);

        #pragma unroll
        for (int sub = 0; sub < 2; sub++){
            const uint32_t* Ys = Yb + sub*32*80;

            // gemm1 + softmax: S already in log2-domain (Wq pre-scaled)
            uint32_t eh[4][2];
            #pragma unroll
            for (int ni = 0; ni < 4; ni++){
                float cs[4] = {0.f, 0.f, 0.f, 0.f};
                #pragma unroll
                for (int kk2 = 0; kk2 < 4; kk2++){
                    uint4 r = *(const uint4*)(Ys + (ni*8 + g)*80 + kk2*16 + tq*4);
                    mma16h(cs, xa[kk2].x, xb[kk2].x, xa[kk2].z, xb[kk2].z, r.x, r.z);
                    mma16h(cs, xa[kk2].y, xb[kk2].y, xa[kk2].w, xb[kk2].w, r.y, r.w);
                }
                eh[ni][0] = ex2h2(packh2(cs[0], cs[1]));
                eh[ni][1] = ex2h2(packh2(cs[2], cs[3]));
            }

            // rowsum via ones-mma
            mma16h(acc_rs, eh[0][0], eh[0][1], eh[1][0], eh[1][1], ONESW, ONESW);
            mma16h(acc_rs, eh[2][0], eh[2][1], eh[3][0], eh[3][1], ONESW, ONESW);

            // gemm2
            #pragma unroll
            for (int n2 = 0; n2 < 16; n2++){
                uint4 r = *(const uint4*)(Pb + (n2*8 + g)*48 + sub*16 + tq*4);
                mma16h(acc[n2], eh[0][0], eh[0][1], eh[1][0], eh[1][1], r.x, r.z);
                mma16h(acc[n2], eh[2][0], eh[2][1], eh[3][0], eh[3][1], r.y, r.w);
            }
        }
        buf ^= 1;
    }

    // normalize + store perm32
    float i0 = 1.0f / acc_rs[0], i1 = 1.0f / acc_rs[2];
    int b = bh >> 3, h = bh & 7;
    int mg = m0 + w*16 + g;
    uint32_t* o0 = (uint32_t*)Mid + (((size_t)(b*M + mg    )*HEADS + h) << 6);
    uint32_t* o8 = (uint32_t*)Mid + (((size_t)(b*M + mg + 8)*HEADS + h) << 6);
    #pragma unroll
    for (int n2 = 0; n2 < 16; n2++){
        int col = n2*8 + 2*tq;
        int wrd = ((col >> 5) << 4) + perm_w(col & 31);
        o0[wrd] = packh2(acc[n2][0]*i0, acc[n2][1]*i0);
        o8[wrd] = packh2(acc[n2][2]*i1, acc[n2][3]*i1);
    }
}

// ================= merged output projection (fp16 cp.async, 2-stage) =================
__global__ void __launch_bounds__(256)
outproj_kernel(const float* __restrict__ bo1, const float* __restrict__ bo2,
               float* __restrict__ out){
    __shared__ uint32_t As[2][128*16];
    __shared__ uint32_t Bs[2][64*16];
    const int bx = blockIdx.x;
    const bool isD = (bx >= 64);
    const int m0 = (isD ? bx - 64 : bx) * 128;
    const int n0 = blockIdx.y * 64;
    const __half* Xh = isD ? g_Dmid : g_Pmid;
    const __half* Wh = isD ? g_Wo2h : g_Wo1h;
    const float* bias = isD ? bo2 : bo1;
    float* outp = out + (isD ? (size_t)BATCH*NQ*DH : 0);
    const int tid = threadIdx.x, w = tid >> 5, lane = tid & 31;
    const int g = lane >> 2, tq = lane & 3;
    const int wm = w >> 1, wn = w & 1;
    const uint32_t* Xw = (const uint32_t*)Xh + (size_t)m0*512;
    const uint32_t* Ww = (const uint32_t*)Wh + (size_t)n0*512;
    uint32_t sa = (uint32_t)__cvta_generic_to_shared(&As[0][0]);
    uint32_t sb = (uint32_t)__cvta_generic_to_shared(&Bs[0][0]);

    float c[2][4][4] = {};
    {
        #pragma unroll
        for (int i = 0; i < 2; i++){
            int u = tid + i*256; int r = u >> 2, q = u & 3;
            cpa16(sa + (r*16 + q*4)*4, Xw + (size_t)r*512 + q*4);
        }
        { int r = tid >> 2, q = tid & 3;
          cpa16(sb + (r*16 + q*4)*4, Ww + (size_t)r*512 + q*4); }
        cpa_commit();
    }

    int buf = 0;
    for (int kt = 0; kt < 32; kt++){
        cpa_wait0();
        __syncthreads();
        if (kt + 1 < 32){
            int nb = buf ^ 1;
            #pragma unroll
            for (int i = 0; i < 2; i++){
                int u = tid + i*256; int r = u >> 2, q = u & 3;
                cpa16(sa + (nb*2048 + r*16 + q*4)*4, Xw + (size_t)r*512 + (kt+1)*16 + q*4);
            }
            { int r = tid >> 2, q = tid & 3;
              cpa16(sb + (nb*1024 + r*16 + q*4)*4, Ww + (size_t)r*512 + (kt+1)*16 + q*4); }
            cpa_commit();
        }
        const uint32_t* A = &As[buf][0];
        const uint32_t* B = &Bs[buf][0];
        uint4 xa[2], xb[2];
        #pragma unroll
        for (int mi = 0; mi < 2; mi++){
            xa[mi] = *(const uint4*)(A + (wm*32+mi*16+g)*16 + tq*4);
            xb[mi] = *(const uint4*)(A + (wm*32+mi*16+g+8)*16 + tq*4);
        }
        #pragma unroll
        for (int ni = 0; ni < 4; ni++){
            uint4 bb = *(const uint4*)(B + (wn*32+ni*8+g)*16 + tq*4);
            #pragma unroll
            for (int mi = 0; mi < 2; mi++){
                mma16h(c[mi][ni], xa[mi].x, xb[mi].x, xa[mi].z, xb[mi].z, bb.x, bb.z);
                mma16h(c[mi][ni], xa[mi].y, xb[mi].y, xa[mi].w, xb[mi].w, bb.y, bb.w);
            }
        }
        buf ^= 1;
    }

    #pragma unroll
    for (int mi=0;mi<2;mi++)
    #pragma unroll
    for (int hh=0;hh<2;hh++)
    #pragma unroll
    for (int ni=0;ni<4;ni++)
    #pragma unroll
    for (int cc=0;cc<2;cc++){
        int row = m0 + wm*32 + mi*16 + g + hh*8;
        int col = n0 + wn*32 + ni*8 + tq*2 + cc;
        outp[((size_t)row << 7) + col] = c[mi][ni][hh*2+cc] + bias[col];
    }
}

// ---------------- launch ----------------
extern "C" void kernel_launch(void* const* d_in, const int* in_sizes, int n_in,
                              void* d_out, int out_size){
    const float* queries = (const float*)d_in[0];
    const float* keys    = (const float*)d_in[1];
    const float* Wq  = (const float*)d_in[2];
    const float* bq  = (const float*)d_in[3];
    const float* Wk  = (const float*)d_in[4];
    const float* bk  = (const float*)d_in[5];
    const float* Wp  = (const float*)d_in[6];
    const float* bp  = (const float*)d_in[7];
    const float* Wg  = (const float*)d_in[8];
    const float* bg  = (const float*)d_in[9];
    const float* Wo1 = (const float*)d_in[10];
    const float* bo1 = (const float*)d_in[11];
    const float* Wo2 = (const float*)d_in[12];
    const float* bo2 = (const float*)d_in[13];
    float* out = (float*)d_out;

    cudaFuncSetAttribute(proj_kernel,  cudaFuncAttributeMaxDynamicSharedMemorySize, PRJ_BYTES);
    cudaFuncSetAttribute(flash_kernel, cudaFuncAttributeMaxDynamicSharedMemorySize, FL_BYTES);

    conv_all_kernel<<<dim3(4096, 8), 256>>>(queries, keys, Wq, Wk, Wp, Wg, Wo1, Wo2);

    proj_kernel<<<dim3(192, 16), 256, PRJ_BYTES>>>(bq, bk, bp, bg);

    flash_kernel<<<dim3(12, BH), 256, FL_BYTES>>>();

    outproj_kernel<<<dim3(192, 2), 256>>>(bo1, bo2, out);
}